// round 9
// baseline (speedup 1.0000x reference)
#include <cuda_runtime.h>
#include <cuda_bf16.h>
#include <math.h>
#include <stdint.h>

#define BV 2
#define TV 2048
#define CV 1024
#define HV 16
#define DHV 64
#define MV (BV * TV)   // 4096

// ---------------------------------------------------------------------------
// Scratch (__device__ globals; allocation-free rule)
// ---------------------------------------------------------------------------
__device__ float g_q[(size_t)MV * CV];
__device__ float g_k[(size_t)MV * CV];
__device__ float g_v[(size_t)MV * CV];

__device__ __nv_bfloat16 g_xh[(size_t)MV * CV];       // x (then normed out) hi
__device__ __nv_bfloat16 g_xl[(size_t)MV * CV];       // x (then normed out) lo
__device__ __nv_bfloat16 g_wh[(size_t)3 * CV * CV];   // Wq,Wk,Wv hi
__device__ __nv_bfloat16 g_wl[(size_t)3 * CV * CV];   // Wq,Wk,Wv lo
__device__ __nv_bfloat16 g_woh[(size_t)CV * CV];      // Wo hi
__device__ __nv_bfloat16 g_wol[(size_t)CV * CV];      // Wo lo

__device__ __nv_bfloat16 g_qh[(size_t)MV * CV];       // roped q hi/lo  [b*T+t][h*64+d]
__device__ __nv_bfloat16 g_ql[(size_t)MV * CV];
__device__ __nv_bfloat16 g_kh[(size_t)MV * CV];       // roped k hi/lo
__device__ __nv_bfloat16 g_kl[(size_t)MV * CV];
__device__ __nv_bfloat16 g_vth[(size_t)MV * CV];      // v^T hi/lo  [bh][d][t]
__device__ __nv_bfloat16 g_vtl[(size_t)MV * CV];

// ---------------------------------------------------------------------------
// helpers
// ---------------------------------------------------------------------------
__device__ __forceinline__ uint32_t smem_to_u32(const void* p) {
    uint32_t a;
    asm("{ .reg .u64 t; cvta.to.shared.u64 t, %1; cvt.u32.u64 %0, t; }"
        : "=r"(a) : "l"(p));
    return a;
}
__device__ __forceinline__ void cp16(uint32_t saddr, const void* g) {
    asm volatile("cp.async.cg.shared.global [%0], [%1], 16;"
                 :: "r"(saddr), "l"(g) : "memory");
}
__device__ __forceinline__ void cp_commit() {
    asm volatile("cp.async.commit_group;" ::: "memory");
}
__device__ __forceinline__ void cp_wait1() {
    asm volatile("cp.async.wait_group 1;" ::: "memory");
}
__device__ __forceinline__ void cp_wait0() {
    asm volatile("cp.async.wait_group 0;" ::: "memory");
}
__device__ __forceinline__ void ldsm4(uint32_t& r0, uint32_t& r1,
                                      uint32_t& r2, uint32_t& r3, uint32_t addr) {
    asm volatile("ldmatrix.sync.aligned.m8n8.x4.shared.b16 {%0,%1,%2,%3}, [%4];"
                 : "=r"(r0), "=r"(r1), "=r"(r2), "=r"(r3) : "r"(addr));
}
__device__ __forceinline__ void mma_bf16(float* c, const uint32_t* a, const uint32_t* b) {
    asm volatile(
        "mma.sync.aligned.m16n8k16.row.col.f32.bf16.bf16.f32 "
        "{%0,%1,%2,%3}, {%4,%5,%6,%7}, {%8,%9}, {%0,%1,%2,%3};"
        : "+f"(c[0]), "+f"(c[1]), "+f"(c[2]), "+f"(c[3])
        : "r"(a[0]), "r"(a[1]), "r"(a[2]), "r"(a[3]), "r"(b[0]), "r"(b[1]));
}
__device__ __forceinline__ float fast_exp2(float x) {
    float r;
    asm("ex2.approx.f32 %0, %1;" : "=f"(r) : "f"(x));
    return r;
}
// pack: result = {lo, hi} bf16x2
__device__ __forceinline__ uint32_t pack_bf16(float lo, float hi) {
    uint32_t r;
    asm("cvt.rn.bf16x2.f32 %0, %1, %2;" : "=r"(r) : "f"(hi), "f"(lo));
    return r;
}
__device__ __forceinline__ float bf16lo_f32(uint32_t p) { return __uint_as_float(p << 16); }
__device__ __forceinline__ float bf16hi_f32(uint32_t p) { return __uint_as_float(p & 0xffff0000u); }

// ---------------------------------------------------------------------------
// fp32 -> (bf16 hi, bf16 lo) split. 4 elements per thread.
// ---------------------------------------------------------------------------
__global__ void conv_hilo(const float* __restrict__ src,
                          __nv_bfloat16* __restrict__ hi,
                          __nv_bfloat16* __restrict__ lo, int n4)
{
    int i = blockIdx.x * blockDim.x + threadIdx.x;
    if (i >= n4) return;
    float4 v = ((const float4*)src)[i];
    __nv_bfloat16 h0 = __float2bfloat16(v.x);
    __nv_bfloat16 h1 = __float2bfloat16(v.y);
    __nv_bfloat16 h2 = __float2bfloat16(v.z);
    __nv_bfloat16 h3 = __float2bfloat16(v.w);
    __nv_bfloat16 l0 = __float2bfloat16(v.x - __bfloat162float(h0));
    __nv_bfloat16 l1 = __float2bfloat16(v.y - __bfloat162float(h1));
    __nv_bfloat16 l2 = __float2bfloat16(v.z - __bfloat162float(h2));
    __nv_bfloat16 l3 = __float2bfloat16(v.w - __bfloat162float(h3));
    ushort4 hv, lv;
    hv.x = __bfloat16_as_ushort(h0); hv.y = __bfloat16_as_ushort(h1);
    hv.z = __bfloat16_as_ushort(h2); hv.w = __bfloat16_as_ushort(h3);
    lv.x = __bfloat16_as_ushort(l0); lv.y = __bfloat16_as_ushort(l1);
    lv.z = __bfloat16_as_ushort(l2); lv.w = __bfloat16_as_ushort(l3);
    ((ushort4*)hi)[i] = hv;
    ((ushort4*)lo)[i] = lv;
}

// ---------------------------------------------------------------------------
// Warp-MMA bf16 GEMM with hi/lo fp32 emulation (unchanged from R6 PASS).
// ---------------------------------------------------------------------------
#define STAGE_BYTES 65536
#define OFF_AH 0
#define OFF_AL 16384
#define OFF_BH 32768
#define OFF_BL 49152
#define GEMM_SMEM (2 * STAGE_BYTES)

__global__ __launch_bounds__(256)
void bfgemm(const __nv_bfloat16* __restrict__ Ah,
            const __nv_bfloat16* __restrict__ Al,
            const __nv_bfloat16* __restrict__ Wh0,
            const __nv_bfloat16* __restrict__ Wl0,
            float* __restrict__ C0, float* __restrict__ C1, float* __restrict__ C2)
{
    extern __shared__ char smem[];
    const uint32_t sb = smem_to_u32(smem);
    const int tid = threadIdx.x;
    const int wid = tid >> 5;
    const int lane = tid & 31;
    const int z = blockIdx.z;

    const __nv_bfloat16* Wh = Wh0 + (size_t)z * CV * CV;
    const __nv_bfloat16* Wl = Wl0 + (size_t)z * CV * CV;
    float* C = (z == 0) ? C0 : ((z == 1) ? C1 : C2);

    const int bm = blockIdx.y * 128;
    const int bn = blockIdx.x * 128;
    const int warp_m = wid >> 1;
    const int warp_n = wid & 1;

    float c[2][8][4];
#pragma unroll
    for (int mb = 0; mb < 2; ++mb)
#pragma unroll
        for (int nb = 0; nb < 8; ++nb)
#pragma unroll
            for (int e = 0; e < 4; ++e) c[mb][nb][e] = 0.f;

    auto issue = [&](int ch, int stage) {
        const int kc0 = ch * 64;
        const uint32_t base = sb + stage * STAGE_BYTES;
#pragma unroll
        for (int it = 0; it < 4; ++it) {
            const int idx = it * 256 + tid;
            const int row = idx >> 3;
            const int colb = (idx & 7) * 16;
            const uint32_t sw = (uint32_t)(row * 128 + (colb ^ ((row & 7) << 4)));
            const size_t gA = (size_t)(bm + row) * CV + kc0 + (colb >> 1);
            const size_t gB = (size_t)(bn + row) * CV + kc0 + (colb >> 1);
            cp16(base + OFF_AH + sw, Ah + gA);
            cp16(base + OFF_AL + sw, Al + gA);
            cp16(base + OFF_BH + sw, Wh + gB);
            cp16(base + OFF_BL + sw, Wl + gB);
        }
        cp_commit();
    };

    issue(0, 0);

    const int a_row16 = lane & 15;
    const int a_koffb = ((lane >> 4) & 1) * 16;
    const int b_rowsel = (lane & 7) + ((lane >> 4) & 1) * 8;
    const int b_koffb = ((lane >> 3) & 1) * 16;

    const int NT = 16;
    for (int ch = 0; ch < NT; ++ch) {
        if (ch + 1 < NT) issue(ch + 1, (ch + 1) & 1);
        if (ch + 1 < NT) cp_wait1(); else cp_wait0();
        __syncthreads();

        const uint32_t base = sb + (ch & 1) * STAGE_BYTES;
#pragma unroll
        for (int ks = 0; ks < 4; ++ks) {
            const int kb = ks * 32;

            uint32_t ah[2][4], al[2][4];
#pragma unroll
            for (int mb = 0; mb < 2; ++mb) {
                const int r = warp_m * 32 + mb * 16 + a_row16;
                const uint32_t ad = base + (uint32_t)(r * 128 +
                                     ((kb + a_koffb) ^ ((r & 7) << 4)));
                ldsm4(ah[mb][0], ah[mb][1], ah[mb][2], ah[mb][3], ad + OFF_AH);
                ldsm4(al[mb][0], al[mb][1], al[mb][2], al[mb][3], ad + OFF_AL);
            }

            uint32_t bh[8][2], bl[8][2];
#pragma unroll
            for (int nq = 0; nq < 4; ++nq) {
                const int r = warp_n * 64 + nq * 16 + b_rowsel;
                const uint32_t bd = base + (uint32_t)(r * 128 +
                                     ((kb + b_koffb) ^ ((r & 7) << 4)));
                uint32_t t0, t1, t2, t3;
                ldsm4(t0, t1, t2, t3, bd + OFF_BH);
                bh[nq * 2][0] = t0; bh[nq * 2][1] = t1;
                bh[nq * 2 + 1][0] = t2; bh[nq * 2 + 1][1] = t3;
                ldsm4(t0, t1, t2, t3, bd + OFF_BL);
                bl[nq * 2][0] = t0; bl[nq * 2][1] = t1;
                bl[nq * 2 + 1][0] = t2; bl[nq * 2 + 1][1] = t3;
            }

#pragma unroll
            for (int mb = 0; mb < 2; ++mb)
#pragma unroll
                for (int nb = 0; nb < 8; ++nb) {
                    mma_bf16(c[mb][nb], ah[mb], bh[nb]);
                    mma_bf16(c[mb][nb], ah[mb], bl[nb]);
                    mma_bf16(c[mb][nb], al[mb], bh[nb]);
                }
        }
        __syncthreads();
    }

    const int gr = lane >> 2;
    const int gc = (lane & 3) * 2;
#pragma unroll
    for (int mb = 0; mb < 2; ++mb) {
        const int row0 = bm + warp_m * 32 + mb * 16 + gr;
#pragma unroll
        for (int nb = 0; nb < 8; ++nb) {
            const int col = bn + warp_n * 64 + nb * 8 + gc;
            *(float2*)(C + (size_t)row0 * CV + col) =
                make_float2(c[mb][nb][0], c[mb][nb][1]);
            *(float2*)(C + (size_t)(row0 + 8) * CV + col) =
                make_float2(c[mb][nb][2], c[mb][nb][3]);
        }
    }
}

// ---------------------------------------------------------------------------
// RoPE on q and k + bf16 hi/lo conversion. Thread per (b,t,h,j<32).
// ---------------------------------------------------------------------------
__global__ void rope_conv()
{
    const int idx = blockIdx.x * blockDim.x + threadIdx.x;
    const int j = idx & 31;
    const int h = (idx >> 5) & (HV - 1);
    const int t = (idx >> 9) & (TV - 1);
    const int b = idx >> 20;

    const float L2_10000 = 13.287712379549449f;
    const float invf = exp2f(-(float)j * (L2_10000 / 32.0f));
    const float ang = (float)t * invf;
    float sn, cs;
    sincosf(ang, &sn, &cs);

    const size_t base = (size_t)(b * TV + t) * CV + h * DHV + j;

    float q1 = g_q[base], q2 = g_q[base + 32];
    float qa = q1 * cs - q2 * sn;
    float qb = q2 * cs + q1 * sn;
    float k1 = g_k[base], k2 = g_k[base + 32];
    float ka = k1 * cs - k2 * sn;
    float kb = k2 * cs + k1 * sn;

    __nv_bfloat16 hqa = __float2bfloat16(qa);
    __nv_bfloat16 hqb = __float2bfloat16(qb);
    __nv_bfloat16 hka = __float2bfloat16(ka);
    __nv_bfloat16 hkb = __float2bfloat16(kb);
    g_qh[base]      = hqa;
    g_qh[base + 32] = hqb;
    g_ql[base]      = __float2bfloat16(qa - __bfloat162float(hqa));
    g_ql[base + 32] = __float2bfloat16(qb - __bfloat162float(hqb));
    g_kh[base]      = hka;
    g_kh[base + 32] = hkb;
    g_kl[base]      = __float2bfloat16(ka - __bfloat162float(hka));
    g_kl[base + 32] = __float2bfloat16(kb - __bfloat162float(hkb));
}

// ---------------------------------------------------------------------------
// v transpose + hi/lo: g_v [b*T+t][h*64+d] -> g_vth/g_vtl [bh][d][t].
// ---------------------------------------------------------------------------
__global__ __launch_bounds__(256)
void vtrans()
{
    __shared__ float vt[64][65];
    const int bh = blockIdx.y;
    const int b = bh >> 4, h = bh & 15;
    const int t0 = blockIdx.x * 64;
    const int tid = threadIdx.x;

#pragma unroll
    for (int it = 0; it < 4; ++it) {
        const int idx = it * 256 + tid;
        const int row = idx >> 4;
        const int c4 = (idx & 15) * 4;
        float4 v = *(const float4*)(g_v + (size_t)(b * TV + t0 + row) * CV + h * DHV + c4);
        vt[row][c4 + 0] = v.x; vt[row][c4 + 1] = v.y;
        vt[row][c4 + 2] = v.z; vt[row][c4 + 3] = v.w;
    }
    __syncthreads();

#pragma unroll
    for (int it = 0; it < 4; ++it) {
        const int idx = it * 256 + tid;
        const int d = idx >> 4;
        const int tc = (idx & 15) * 4;
        float x0 = vt[tc + 0][d], x1 = vt[tc + 1][d];
        float x2 = vt[tc + 2][d], x3 = vt[tc + 3][d];
        uint32_t h01 = pack_bf16(x0, x1);
        uint32_t h23 = pack_bf16(x2, x3);
        float r0 = x0 - bf16lo_f32(h01), r1 = x1 - bf16hi_f32(h01);
        float r2 = x2 - bf16lo_f32(h23), r3 = x3 - bf16hi_f32(h23);
        uint32_t l01 = pack_bf16(r0, r1);
        uint32_t l23 = pack_bf16(r2, r3);
        const size_t off = (size_t)(bh * DHV + d) * TV + t0 + tc;
        *(uint2*)(g_vth + off) = make_uint2(h01, h23);
        *(uint2*)(g_vtl + off) = make_uint2(l01, l23);
    }
}

// ---------------------------------------------------------------------------
// Retention attention on tensor cores, v2:
//  - 128 q rows per CTA (8 warps; warp w owns rows [16w,16w+16))
//  - double-buffered 64-row k/v stages (cp.async, wait_group 1)
//  - causal warp-level skip / full-tile fast path
//  - fused GroupNorm epilogue -> bf16 hi/lo out-proj input
// SMEM: Q hi/lo 32KB + 2 stages x (k hi/lo + v^T hi/lo) 32KB = 96KB.
// ---------------------------------------------------------------------------
#define AQH 0
#define AQL 16384
#define ASTG 32768
#define ASTG_SZ 32768
#define SKH 0
#define SKL 8192
#define SVH 16384
#define SVL 24576
#define ATTN_SMEM (ASTG + 2 * ASTG_SZ)   // 98304

__global__ __launch_bounds__(256)
void retention_mma(const float* __restrict__ gn_w, const float* __restrict__ gn_b)
{
    extern __shared__ char smem[];
    const uint32_t sb = smem_to_u32(smem);
    const int tid = threadIdx.x;
    const int w = tid >> 5;
    const int lane = tid & 31;

    const int qt = (int)(gridDim.x - 1 - blockIdx.x);   // big tiles first
    const int bh = blockIdx.y;
    const int b = bh >> 4, h = bh & 15;
    const int tq0 = qt * 128;
    const int row_base = tq0 + w * 16;

    const int g = lane >> 2;        // accumulator row group
    const int t4 = lane & 3;        // accumulator col group

    const float gamma = 1.0f - __int_as_float((127 - 5 - h) << 23);
    const float l2g = log2f(gamma);
    const float ginv1 = fast_exp2(-l2g);
    const float ginv8 = fast_exp2(-8.0f * l2g);
    const float gpow8 = fast_exp2(8.0f * l2g);
    const float ctf = fast_exp2(-2.0f * (float)t4 * l2g);

    auto issueTile = [&](int kt, int stage) {
        const int tk0 = kt * 64;
        const uint32_t base = sb + ASTG + stage * ASTG_SZ;
#pragma unroll
        for (int it = 0; it < 2; ++it) {
            const int idx = it * 256 + tid;      // 512 slots = 64 rows x 8 chunks
            const int row = idx >> 3;
            const int colb = (idx & 7) * 16;
            const uint32_t sw = (uint32_t)(row * 128 + (colb ^ ((row & 7) << 4)));
            const size_t gk = (size_t)(b * TV + tk0 + row) * CV + h * DHV + (colb >> 1);
            const size_t gv = (size_t)(bh * DHV + row) * TV + tk0 + (colb >> 1);
            cp16(base + SKH + sw, g_kh + gk);
            cp16(base + SKL + sw, g_kl + gk);
            cp16(base + SVH + sw, g_vth + gv);
            cp16(base + SVL + sw, g_vtl + gv);
        }
        cp_commit();
    };

    // ---- group 0: q tile (128 rows hi/lo) + ktile 0 ----
#pragma unroll
    for (int it = 0; it < 4; ++it) {
        const int idx = it * 256 + tid;          // 1024 slots
        const int row = idx >> 3;
        const int colb = (idx & 7) * 16;
        const uint32_t sw = (uint32_t)(row * 128 + (colb ^ ((row & 7) << 4)));
        const size_t gq = (size_t)(b * TV + tq0 + row) * CV + h * DHV + (colb >> 1);
        cp16(sb + AQH + sw, g_qh + gq);
        cp16(sb + AQL + sw, g_ql + gq);
    }
    issueTile(0, 0);   // commits group 0 (q + tile0)

    uint32_t qfh[4][4], qfl[4][4];
    float o[8][4];
#pragma unroll
    for (int nb = 0; nb < 8; ++nb)
#pragma unroll
        for (int e = 0; e < 4; ++e) o[nb][e] = 0.f;

    const int b_row = (lane & 7) + ((lane >> 4) & 1) * 8;
    const int b_koffb = ((lane >> 3) & 1) * 16;

    const int NKT = 2 * qt + 2;
    for (int kt = 0; kt < NKT; ++kt) {
        if (kt + 1 < NKT) { issueTile(kt + 1, (kt + 1) & 1); cp_wait1(); }
        else cp_wait0();
        __syncthreads();

        if (kt == 0) {
            // build persistent q fragments (q smem never overwritten)
            const int ar = w * 16 + (lane & 15);
            const int ak = ((lane >> 4) & 1) * 16;
#pragma unroll
            for (int ks = 0; ks < 4; ++ks) {
                const uint32_t ad = sb + (uint32_t)(ar * 128 +
                                     ((ks * 32 + ak) ^ ((ar & 7) << 4)));
                ldsm4(qfh[ks][0], qfh[ks][1], qfh[ks][2], qfh[ks][3], ad + AQH);
                ldsm4(qfl[ks][0], qfl[ks][1], qfl[ks][2], qfl[ks][3], ad + AQL);
            }
        }

        const int tk0 = kt * 64;
        const uint32_t base = sb + ASTG + (kt & 1) * ASTG_SZ;

        if (row_base + 15 >= tk0) {      // warp not fully masked
            // ---- S = q k^T (3-term hi/lo) ----
            float s[8][4];
#pragma unroll
            for (int nb = 0; nb < 8; ++nb)
#pragma unroll
                for (int e = 0; e < 4; ++e) s[nb][e] = 0.f;

#pragma unroll
            for (int ks = 0; ks < 4; ++ks) {
#pragma unroll
                for (int nq = 0; nq < 4; ++nq) {
                    const int r = nq * 16 + b_row;
                    const uint32_t bd = base + (uint32_t)(r * 128 +
                                         ((ks * 32 + b_koffb) ^ ((r & 7) << 4)));
                    uint32_t h0, h1, h2, h3, l0, l1, l2, l3;
                    ldsm4(h0, h1, h2, h3, bd + SKH);
                    ldsm4(l0, l1, l2, l3, bd + SKL);
                    uint32_t bh0[2] = {h0, h1}, bh1[2] = {h2, h3};
                    uint32_t bl0[2] = {l0, l1}, bl1[2] = {l2, l3};
                    mma_bf16(s[nq * 2],     qfh[ks], bh0);
                    mma_bf16(s[nq * 2],     qfh[ks], bl0);
                    mma_bf16(s[nq * 2],     qfl[ks], bh0);
                    mma_bf16(s[nq * 2 + 1], qfh[ks], bh1);
                    mma_bf16(s[nq * 2 + 1], qfh[ks], bl1);
                    mma_bf16(s[nq * 2 + 1], qfl[ks], bh1);
                }
            }

            // ---- decay * scale ----
            const float rf0 = 0.125f * fast_exp2((float)(row_base + g - tk0) * l2g);
            const float rf8 = rf0 * gpow8;
            float cf = ctf;
            if (row_base - tk0 >= 63) {               // full tile: no mask
#pragma unroll
                for (int nb = 0; nb < 8; ++nb) {
                    const float c0f = cf, c1f = cf * ginv1;
                    s[nb][0] *= rf0 * c0f;
                    s[nb][1] *= rf0 * c1f;
                    s[nb][2] *= rf8 * c0f;
                    s[nb][3] *= rf8 * c1f;
                    cf *= ginv8;
                }
            } else {                                   // diagonal tile
                const int r0 = row_base + g - tk0, r1 = r0 + 8;
#pragma unroll
                for (int nb = 0; nb < 8; ++nb) {
                    const int j0 = 8 * nb + 2 * t4;
                    const float c0f = cf, c1f = cf * ginv1;
                    s[nb][0] = (r0 >= j0)     ? s[nb][0] * rf0 * c0f : 0.f;
                    s[nb][1] = (r0 >= j0 + 1) ? s[nb][1] * rf0 * c1f : 0.f;
                    s[nb][2] = (r1 >= j0)     ? s[nb][2] * rf8 * c0f : 0.f;
                    s[nb][3] = (r1 >= j0 + 1) ? s[nb][3] * rf8 * c1f : 0.f;
                    cf *= ginv8;
                }
            }

            // ---- S -> bf16 hi/lo A-fragments ----
            uint32_t sah[4][4], sal[4][4];
#pragma unroll
            for (int kc = 0; kc < 4; ++kc) {
                const int n0 = 2 * kc, n1 = 2 * kc + 1;
                uint32_t p;
                p = pack_bf16(s[n0][0], s[n0][1]);
                sah[kc][0] = p;
                sal[kc][0] = pack_bf16(s[n0][0] - bf16lo_f32(p), s[n0][1] - bf16hi_f32(p));
                p = pack_bf16(s[n0][2], s[n0][3]);
                sah[kc][1] = p;
                sal[kc][1] = pack_bf16(s[n0][2] - bf16lo_f32(p), s[n0][3] - bf16hi_f32(p));
                p = pack_bf16(s[n1][0], s[n1][1]);
                sah[kc][2] = p;
                sal[kc][2] = pack_bf16(s[n1][0] - bf16lo_f32(p), s[n1][1] - bf16hi_f32(p));
                p = pack_bf16(s[n1][2], s[n1][3]);
                sah[kc][3] = p;
                sal[kc][3] = pack_bf16(s[n1][2] - bf16lo_f32(p), s[n1][3] - bf16hi_f32(p));
            }

            // ---- O += S v (3-term hi/lo) ----
#pragma unroll
            for (int kc = 0; kc < 4; ++kc) {
#pragma unroll
                for (int nq = 0; nq < 4; ++nq) {
                    const int r = nq * 16 + b_row;
                    const uint32_t bd = base + (uint32_t)(r * 128 +
                                         ((kc * 32 + b_koffb) ^ ((r & 7) << 4)));
                    uint32_t h0, h1, h2, h3, l0, l1, l2, l3;
                    ldsm4(h0, h1, h2, h3, bd + SVH);
                    ldsm4(l0, l1, l2, l3, bd + SVL);
                    uint32_t vh0[2] = {h0, h1}, vh1[2] = {h2, h3};
                    uint32_t vl0[2] = {l0, l1}, vl1[2] = {l2, l3};
                    mma_bf16(o[nq * 2],     sah[kc], vh0);
                    mma_bf16(o[nq * 2],     sah[kc], vl0);
                    mma_bf16(o[nq * 2],     sal[kc], vh0);
                    mma_bf16(o[nq * 2 + 1], sah[kc], vh1);
                    mma_bf16(o[nq * 2 + 1], sah[kc], vl1);
                    mma_bf16(o[nq * 2 + 1], sal[kc], vh1);
                }
            }
        }
        __syncthreads();   // stage reuse barrier
    }

    // ---- fused GroupNorm + bf16 hi/lo store into out-proj input ----
    float sum0 = 0.f, sq0 = 0.f, sum1 = 0.f, sq1 = 0.f;
#pragma unroll
    for (int nb = 0; nb < 8; ++nb) {
        sum0 += o[nb][0] + o[nb][1];
        sq0  += o[nb][0] * o[nb][0] + o[nb][1] * o[nb][1];
        sum1 += o[nb][2] + o[nb][3];
        sq1  += o[nb][2] * o[nb][2] + o[nb][3] * o[nb][3];
    }
#pragma unroll
    for (int off = 1; off < 4; off <<= 1) {
        sum0 += __shfl_xor_sync(0xffffffffu, sum0, off);
        sq0  += __shfl_xor_sync(0xffffffffu, sq0,  off);
        sum1 += __shfl_xor_sync(0xffffffffu, sum1, off);
        sq1  += __shfl_xor_sync(0xffffffffu, sq1,  off);
    }
    const float invn = 1.0f / 64.0f;
    const float mean0 = sum0 * invn;
    const float mean1 = sum1 * invn;
    const float rs0 = rsqrtf(sq0 * invn - mean0 * mean0 + 1e-5f);
    const float rs1 = rsqrtf(sq1 * invn - mean1 * mean1 + 1e-5f);

    const int row0 = row_base + g;
    const size_t base0 = (size_t)(b * TV + row0) * CV + h * DHV;
    const size_t base1 = base0 + (size_t)8 * CV;

#pragma unroll
    for (int nb = 0; nb < 8; ++nb) {
        const int d0 = 8 * nb + 2 * t4;
        const float2 wv = *(const float2*)(gn_w + h * DHV + d0);
        const float2 bv = *(const float2*)(gn_b + h * DHV + d0);
        float y00 = (o[nb][0] - mean0) * rs0 * wv.x + bv.x;
        float y01 = (o[nb][1] - mean0) * rs0 * wv.y + bv.y;
        float y10 = (o[nb][2] - mean1) * rs1 * wv.x + bv.x;
        float y11 = (o[nb][3] - mean1) * rs1 * wv.y + bv.y;

        uint32_t p0 = pack_bf16(y00, y01);
        uint32_t q0 = pack_bf16(y00 - bf16lo_f32(p0), y01 - bf16hi_f32(p0));
        uint32_t p1 = pack_bf16(y10, y11);
        uint32_t q1 = pack_bf16(y10 - bf16lo_f32(p1), y11 - bf16hi_f32(p1));

        *(uint32_t*)(g_xh + base0 + d0) = p0;
        *(uint32_t*)(g_xl + base0 + d0) = q0;
        *(uint32_t*)(g_xh + base1 + d0) = p1;
        *(uint32_t*)(g_xl + base1 + d0) = q1;
    }
}

// ---------------------------------------------------------------------------
extern "C" void kernel_launch(void* const* d_in, const int* in_sizes, int n_in,
                              void* d_out, int out_size)
{
    const float* x   = (const float*)d_in[0];
    const float* Wq  = (const float*)d_in[1];
    const float* Wk  = (const float*)d_in[2];
    const float* Wv  = (const float*)d_in[3];
    const float* Wo  = (const float*)d_in[4];
    const float* gnw = (const float*)d_in[5];
    const float* gnb = (const float*)d_in[6];
    float* out = (float*)d_out;

    float *q, *k, *v;
    __nv_bfloat16 *xh, *xl, *wh, *wl, *woh, *wol;
    cudaGetSymbolAddress((void**)&q, g_q);
    cudaGetSymbolAddress((void**)&k, g_k);
    cudaGetSymbolAddress((void**)&v, g_v);
    cudaGetSymbolAddress((void**)&xh, g_xh);
    cudaGetSymbolAddress((void**)&xl, g_xl);
    cudaGetSymbolAddress((void**)&wh, g_wh);
    cudaGetSymbolAddress((void**)&wl, g_wl);
    cudaGetSymbolAddress((void**)&woh, g_woh);
    cudaGetSymbolAddress((void**)&wol, g_wol);

    cudaFuncSetAttribute(bfgemm,
                         cudaFuncAttributeMaxDynamicSharedMemorySize, GEMM_SMEM);
    cudaFuncSetAttribute(retention_mma,
                         cudaFuncAttributeMaxDynamicSharedMemorySize, ATTN_SMEM);

    const int WN4 = CV * CV / 4;
    const int XN4 = MV * CV / 4;

    // 0) hi/lo bf16 splits of inputs
    conv_hilo<<<XN4 / 256, 256>>>(x, xh, xl, XN4);
    conv_hilo<<<WN4 / 256, 256>>>(Wq, wh,                       wl,                       WN4);
    conv_hilo<<<WN4 / 256, 256>>>(Wk, wh + (size_t)CV * CV,     wl + (size_t)CV * CV,     WN4);
    conv_hilo<<<WN4 / 256, 256>>>(Wv, wh + (size_t)2 * CV * CV, wl + (size_t)2 * CV * CV, WN4);
    conv_hilo<<<WN4 / 256, 256>>>(Wo, woh, wol, WN4);

    // 1) QKV projections (tensor cores)
    bfgemm<<<dim3(CV / 128, MV / 128, 3), 256, GEMM_SMEM>>>(xh, xl, wh, wl, q, k, v);
    // 2) RoPE + bf16 hi/lo q,k
    rope_conv<<<(BV * TV * HV * 32) / 256, 256>>>();
    // 3) v transpose + hi/lo
    vtrans<<<dim3(TV / 64, BV * HV), 256>>>();
    // 4) Retention on tensor cores + fused GroupNorm -> g_xh/g_xl
    retention_mma<<<dim3(TV / 128, BV * HV), 256, ATTN_SMEM>>>(gnw, gnb);
    // 5) Output projection (tensor cores)
    bfgemm<<<dim3(CV / 128, MV / 128, 1), 256, GEMM_SMEM>>>(xh, xl, woh, wol, out, out, out);
}

// round 12
// speedup vs baseline: 1.0387x; 1.0387x over previous
#include <cuda_runtime.h>
#include <cuda_bf16.h>
#include <math.h>
#include <stdint.h>

#define BV 2
#define TV 2048
#define CV 1024
#define HV 16
#define DHV 64
#define MV (BV * TV)   // 4096

// ---------------------------------------------------------------------------
// Scratch (__device__ globals; allocation-free rule)
// ---------------------------------------------------------------------------
__device__ float g_q[(size_t)MV * CV];
__device__ float g_k[(size_t)MV * CV];
__device__ float g_v[(size_t)MV * CV];

__device__ __nv_bfloat16 g_xh[(size_t)MV * CV];       // x (then normed out) hi
__device__ __nv_bfloat16 g_xl[(size_t)MV * CV];       // x (then normed out) lo
__device__ __nv_bfloat16 g_wh[(size_t)3 * CV * CV];   // Wq,Wk,Wv hi
__device__ __nv_bfloat16 g_wl[(size_t)3 * CV * CV];   // Wq,Wk,Wv lo
__device__ __nv_bfloat16 g_woh[(size_t)CV * CV];      // Wo hi
__device__ __nv_bfloat16 g_wol[(size_t)CV * CV];      // Wo lo

__device__ __nv_bfloat16 g_qh[(size_t)MV * CV];       // roped q hi/lo  [b*T+t][h*64+d]
__device__ __nv_bfloat16 g_ql[(size_t)MV * CV];
__device__ __nv_bfloat16 g_kh[(size_t)MV * CV];       // roped k hi/lo
__device__ __nv_bfloat16 g_kl[(size_t)MV * CV];
__device__ __nv_bfloat16 g_vth[(size_t)MV * CV];      // v^T hi/lo  [bh][d][t]
__device__ __nv_bfloat16 g_vtl[(size_t)MV * CV];

// ---------------------------------------------------------------------------
// helpers
// ---------------------------------------------------------------------------
__device__ __forceinline__ uint32_t smem_to_u32(const void* p) {
    uint32_t a;
    asm("{ .reg .u64 t; cvta.to.shared.u64 t, %1; cvt.u32.u64 %0, t; }"
        : "=r"(a) : "l"(p));
    return a;
}
__device__ __forceinline__ void cp16(uint32_t saddr, const void* g) {
    asm volatile("cp.async.cg.shared.global [%0], [%1], 16;"
                 :: "r"(saddr), "l"(g) : "memory");
}
__device__ __forceinline__ void cp_commit() {
    asm volatile("cp.async.commit_group;" ::: "memory");
}
__device__ __forceinline__ void cp_wait1() {
    asm volatile("cp.async.wait_group 1;" ::: "memory");
}
__device__ __forceinline__ void cp_wait0() {
    asm volatile("cp.async.wait_group 0;" ::: "memory");
}
__device__ __forceinline__ void ldsm4(uint32_t& r0, uint32_t& r1,
                                      uint32_t& r2, uint32_t& r3, uint32_t addr) {
    asm volatile("ldmatrix.sync.aligned.m8n8.x4.shared.b16 {%0,%1,%2,%3}, [%4];"
                 : "=r"(r0), "=r"(r1), "=r"(r2), "=r"(r3) : "r"(addr));
}
__device__ __forceinline__ void mma_bf16(float* c, const uint32_t* a, const uint32_t* b) {
    asm volatile(
        "mma.sync.aligned.m16n8k16.row.col.f32.bf16.bf16.f32 "
        "{%0,%1,%2,%3}, {%4,%5,%6,%7}, {%8,%9}, {%0,%1,%2,%3};"
        : "+f"(c[0]), "+f"(c[1]), "+f"(c[2]), "+f"(c[3])
        : "r"(a[0]), "r"(a[1]), "r"(a[2]), "r"(a[3]), "r"(b[0]), "r"(b[1]));
}
__device__ __forceinline__ float fast_exp2(float x) {
    float r;
    asm("ex2.approx.f32 %0, %1;" : "=f"(r) : "f"(x));
    return r;
}
// pack: result = {lo, hi} bf16x2
__device__ __forceinline__ uint32_t pack_bf16(float lo, float hi) {
    uint32_t r;
    asm("cvt.rn.bf16x2.f32 %0, %1, %2;" : "=r"(r) : "f"(hi), "f"(lo));
    return r;
}
__device__ __forceinline__ float bf16lo_f32(uint32_t p) { return __uint_as_float(p << 16); }
__device__ __forceinline__ float bf16hi_f32(uint32_t p) { return __uint_as_float(p & 0xffff0000u); }

// ---------------------------------------------------------------------------
// fp32 -> (bf16 hi, bf16 lo) split. 4 elements per thread.
// ---------------------------------------------------------------------------
__global__ void conv_hilo(const float* __restrict__ src,
                          __nv_bfloat16* __restrict__ hi,
                          __nv_bfloat16* __restrict__ lo, int n4)
{
    int i = blockIdx.x * blockDim.x + threadIdx.x;
    if (i >= n4) return;
    float4 v = ((const float4*)src)[i];
    __nv_bfloat16 h0 = __float2bfloat16(v.x);
    __nv_bfloat16 h1 = __float2bfloat16(v.y);
    __nv_bfloat16 h2 = __float2bfloat16(v.z);
    __nv_bfloat16 h3 = __float2bfloat16(v.w);
    __nv_bfloat16 l0 = __float2bfloat16(v.x - __bfloat162float(h0));
    __nv_bfloat16 l1 = __float2bfloat16(v.y - __bfloat162float(h1));
    __nv_bfloat16 l2 = __float2bfloat16(v.z - __bfloat162float(h2));
    __nv_bfloat16 l3 = __float2bfloat16(v.w - __bfloat162float(h3));
    ushort4 hv, lv;
    hv.x = __bfloat16_as_ushort(h0); hv.y = __bfloat16_as_ushort(h1);
    hv.z = __bfloat16_as_ushort(h2); hv.w = __bfloat16_as_ushort(h3);
    lv.x = __bfloat16_as_ushort(l0); lv.y = __bfloat16_as_ushort(l1);
    lv.z = __bfloat16_as_ushort(l2); lv.w = __bfloat16_as_ushort(l3);
    ((ushort4*)hi)[i] = hv;
    ((ushort4*)lo)[i] = lv;
}

// ---------------------------------------------------------------------------
// Warp-MMA bf16 GEMM with hi/lo fp32 emulation (unchanged from R6 PASS).
// ---------------------------------------------------------------------------
#define STAGE_BYTES 65536
#define OFF_AH 0
#define OFF_AL 16384
#define OFF_BH 32768
#define OFF_BL 49152
#define GEMM_SMEM (2 * STAGE_BYTES)

__global__ __launch_bounds__(256)
void bfgemm(const __nv_bfloat16* __restrict__ Ah,
            const __nv_bfloat16* __restrict__ Al,
            const __nv_bfloat16* __restrict__ Wh0,
            const __nv_bfloat16* __restrict__ Wl0,
            float* __restrict__ C0, float* __restrict__ C1, float* __restrict__ C2)
{
    extern __shared__ char smem[];
    const uint32_t sb = smem_to_u32(smem);
    const int tid = threadIdx.x;
    const int wid = tid >> 5;
    const int lane = tid & 31;
    const int z = blockIdx.z;

    const __nv_bfloat16* Wh = Wh0 + (size_t)z * CV * CV;
    const __nv_bfloat16* Wl = Wl0 + (size_t)z * CV * CV;
    float* C = (z == 0) ? C0 : ((z == 1) ? C1 : C2);

    const int bm = blockIdx.y * 128;
    const int bn = blockIdx.x * 128;
    const int warp_m = wid >> 1;
    const int warp_n = wid & 1;

    float c[2][8][4];
#pragma unroll
    for (int mb = 0; mb < 2; ++mb)
#pragma unroll
        for (int nb = 0; nb < 8; ++nb)
#pragma unroll
            for (int e = 0; e < 4; ++e) c[mb][nb][e] = 0.f;

    auto issue = [&](int ch, int stage) {
        const int kc0 = ch * 64;
        const uint32_t base = sb + stage * STAGE_BYTES;
#pragma unroll
        for (int it = 0; it < 4; ++it) {
            const int idx = it * 256 + tid;
            const int row = idx >> 3;
            const int colb = (idx & 7) * 16;
            const uint32_t sw = (uint32_t)(row * 128 + (colb ^ ((row & 7) << 4)));
            const size_t gA = (size_t)(bm + row) * CV + kc0 + (colb >> 1);
            const size_t gB = (size_t)(bn + row) * CV + kc0 + (colb >> 1);
            cp16(base + OFF_AH + sw, Ah + gA);
            cp16(base + OFF_AL + sw, Al + gA);
            cp16(base + OFF_BH + sw, Wh + gB);
            cp16(base + OFF_BL + sw, Wl + gB);
        }
        cp_commit();
    };

    issue(0, 0);

    const int a_row16 = lane & 15;
    const int a_koffb = ((lane >> 4) & 1) * 16;
    const int b_rowsel = (lane & 7) + ((lane >> 4) & 1) * 8;
    const int b_koffb = ((lane >> 3) & 1) * 16;

    const int NT = 16;
    for (int ch = 0; ch < NT; ++ch) {
        if (ch + 1 < NT) issue(ch + 1, (ch + 1) & 1);
        if (ch + 1 < NT) cp_wait1(); else cp_wait0();
        __syncthreads();

        const uint32_t base = sb + (ch & 1) * STAGE_BYTES;
#pragma unroll
        for (int ks = 0; ks < 4; ++ks) {
            const int kb = ks * 32;

            uint32_t ah[2][4], al[2][4];
#pragma unroll
            for (int mb = 0; mb < 2; ++mb) {
                const int r = warp_m * 32 + mb * 16 + a_row16;
                const uint32_t ad = base + (uint32_t)(r * 128 +
                                     ((kb + a_koffb) ^ ((r & 7) << 4)));
                ldsm4(ah[mb][0], ah[mb][1], ah[mb][2], ah[mb][3], ad + OFF_AH);
                ldsm4(al[mb][0], al[mb][1], al[mb][2], al[mb][3], ad + OFF_AL);
            }

            uint32_t bh[8][2], bl[8][2];
#pragma unroll
            for (int nq = 0; nq < 4; ++nq) {
                const int r = warp_n * 64 + nq * 16 + b_rowsel;
                const uint32_t bd = base + (uint32_t)(r * 128 +
                                     ((kb + b_koffb) ^ ((r & 7) << 4)));
                uint32_t t0, t1, t2, t3;
                ldsm4(t0, t1, t2, t3, bd + OFF_BH);
                bh[nq * 2][0] = t0; bh[nq * 2][1] = t1;
                bh[nq * 2 + 1][0] = t2; bh[nq * 2 + 1][1] = t3;
                ldsm4(t0, t1, t2, t3, bd + OFF_BL);
                bl[nq * 2][0] = t0; bl[nq * 2][1] = t1;
                bl[nq * 2 + 1][0] = t2; bl[nq * 2 + 1][1] = t3;
            }

#pragma unroll
            for (int mb = 0; mb < 2; ++mb)
#pragma unroll
                for (int nb = 0; nb < 8; ++nb) {
                    mma_bf16(c[mb][nb], ah[mb], bh[nb]);
                    mma_bf16(c[mb][nb], ah[mb], bl[nb]);
                    mma_bf16(c[mb][nb], al[mb], bh[nb]);
                }
        }
        __syncthreads();
    }

    const int gr = lane >> 2;
    const int gc = (lane & 3) * 2;
#pragma unroll
    for (int mb = 0; mb < 2; ++mb) {
        const int row0 = bm + warp_m * 32 + mb * 16 + gr;
#pragma unroll
        for (int nb = 0; nb < 8; ++nb) {
            const int col = bn + warp_n * 64 + nb * 8 + gc;
            *(float2*)(C + (size_t)row0 * CV + col) =
                make_float2(c[mb][nb][0], c[mb][nb][1]);
            *(float2*)(C + (size_t)(row0 + 8) * CV + col) =
                make_float2(c[mb][nb][2], c[mb][nb][3]);
        }
    }
}

// ---------------------------------------------------------------------------
// RoPE on q and k + bf16 hi/lo conversion. Thread per (b,t,h,j<32).
// ---------------------------------------------------------------------------
__global__ void rope_conv()
{
    const int idx = blockIdx.x * blockDim.x + threadIdx.x;
    const int j = idx & 31;
    const int h = (idx >> 5) & (HV - 1);
    const int t = (idx >> 9) & (TV - 1);
    const int b = idx >> 20;

    const float L2_10000 = 13.287712379549449f;
    const float invf = exp2f(-(float)j * (L2_10000 / 32.0f));
    const float ang = (float)t * invf;
    float sn, cs;
    sincosf(ang, &sn, &cs);

    const size_t base = (size_t)(b * TV + t) * CV + h * DHV + j;

    float q1 = g_q[base], q2 = g_q[base + 32];
    float qa = q1 * cs - q2 * sn;
    float qb = q2 * cs + q1 * sn;
    float k1 = g_k[base], k2 = g_k[base + 32];
    float ka = k1 * cs - k2 * sn;
    float kb = k2 * cs + k1 * sn;

    __nv_bfloat16 hqa = __float2bfloat16(qa);
    __nv_bfloat16 hqb = __float2bfloat16(qb);
    __nv_bfloat16 hka = __float2bfloat16(ka);
    __nv_bfloat16 hkb = __float2bfloat16(kb);
    g_qh[base]      = hqa;
    g_qh[base + 32] = hqb;
    g_ql[base]      = __float2bfloat16(qa - __bfloat162float(hqa));
    g_ql[base + 32] = __float2bfloat16(qb - __bfloat162float(hqb));
    g_kh[base]      = hka;
    g_kh[base + 32] = hkb;
    g_kl[base]      = __float2bfloat16(ka - __bfloat162float(hka));
    g_kl[base + 32] = __float2bfloat16(kb - __bfloat162float(hkb));
}

// ---------------------------------------------------------------------------
// v transpose + hi/lo: g_v [b*T+t][h*64+d] -> g_vth/g_vtl [bh][d][t].
// ---------------------------------------------------------------------------
__global__ __launch_bounds__(256)
void vtrans()
{
    __shared__ float vt[64][65];
    const int bh = blockIdx.y;
    const int b = bh >> 4, h = bh & 15;
    const int t0 = blockIdx.x * 64;
    const int tid = threadIdx.x;

#pragma unroll
    for (int it = 0; it < 4; ++it) {
        const int idx = it * 256 + tid;
        const int row = idx >> 4;
        const int c4 = (idx & 15) * 4;
        float4 v = *(const float4*)(g_v + (size_t)(b * TV + t0 + row) * CV + h * DHV + c4);
        vt[row][c4 + 0] = v.x; vt[row][c4 + 1] = v.y;
        vt[row][c4 + 2] = v.z; vt[row][c4 + 3] = v.w;
    }
    __syncthreads();

#pragma unroll
    for (int it = 0; it < 4; ++it) {
        const int idx = it * 256 + tid;
        const int d = idx >> 4;
        const int tc = (idx & 15) * 4;
        float x0 = vt[tc + 0][d], x1 = vt[tc + 1][d];
        float x2 = vt[tc + 2][d], x3 = vt[tc + 3][d];
        uint32_t h01 = pack_bf16(x0, x1);
        uint32_t h23 = pack_bf16(x2, x3);
        float r0 = x0 - bf16lo_f32(h01), r1 = x1 - bf16hi_f32(h01);
        float r2 = x2 - bf16lo_f32(h23), r3 = x3 - bf16hi_f32(h23);
        uint32_t l01 = pack_bf16(r0, r1);
        uint32_t l23 = pack_bf16(r2, r3);
        const size_t off = (size_t)(bh * DHV + d) * TV + t0 + tc;
        *(uint2*)(g_vth + off) = make_uint2(h01, h23);
        *(uint2*)(g_vtl + off) = make_uint2(l01, l23);
    }
}

// ---------------------------------------------------------------------------
// Retention attention on tensor cores (R8 shape: 64 q-rows, 4 warps, 48KB,
// 4 CTAs/SM) + software-pipelined k/v loads via split cp.async commit groups.
// FIXED vs R11: cp.async.wait_group only orders the ISSUING thread's copies;
// every wait that precedes a cross-thread smem read is now followed by
// __syncthreads() (wait -> barrier -> read), matching the proven preload
// pattern. Pipeline overlap is preserved.
// Fused GroupNorm epilogue writes bf16 hi/lo out-proj input.
// ---------------------------------------------------------------------------
#define AQH 0
#define AQL 8192
#define AKH 16384
#define AKL 24576
#define AVH 32768
#define AVL 40960
#define ATTN_SMEM 49152

__global__ __launch_bounds__(128)
void retention_mma(const float* __restrict__ gn_w, const float* __restrict__ gn_b)
{
    extern __shared__ char smem[];
    const uint32_t sb = smem_to_u32(smem);
    const int tid = threadIdx.x;
    const int w = tid >> 5;
    const int lane = tid & 31;

    const int qt = (int)(gridDim.x - 1 - blockIdx.x);   // big tiles first
    const int bh = blockIdx.y;
    const int b = bh >> 4, h = bh & 15;
    const int tq0 = qt * 64;

    const int g = lane >> 2;        // accumulator row group
    const int t4 = lane & 3;        // accumulator col group

    const float gamma = 1.0f - __int_as_float((127 - 5 - h) << 23);
    const float l2g = log2f(gamma);
    const float ginv1 = fast_exp2(-l2g);
    const float ginv8 = fast_exp2(-8.0f * l2g);
    const float gpow8 = fast_exp2(8.0f * l2g);
    const float ctf = fast_exp2(-2.0f * (float)t4 * l2g);

    // ---- commit-group loaders (16KB each: hi+lo of one 64x64 tile) ----
    auto issueK = [&](int kt) {
        const int tk0 = kt * 64;
#pragma unroll
        for (int it = 0; it < 4; ++it) {
            const int idx = it * 128 + tid;      // 512 slots
            const int row = idx >> 3;
            const int colb = (idx & 7) * 16;
            const uint32_t sw = (uint32_t)(row * 128 + (colb ^ ((row & 7) << 4)));
            const size_t gk = (size_t)(b * TV + tk0 + row) * CV + h * DHV + (colb >> 1);
            cp16(sb + AKH + sw, g_kh + gk);
            cp16(sb + AKL + sw, g_kl + gk);
        }
        cp_commit();
    };
    auto issueV = [&](int kt) {
        const int tk0 = kt * 64;
#pragma unroll
        for (int it = 0; it < 4; ++it) {
            const int idx = it * 128 + tid;
            const int row = idx >> 3;
            const int colb = (idx & 7) * 16;
            const uint32_t sw = (uint32_t)(row * 128 + (colb ^ ((row & 7) << 4)));
            const size_t gv = (size_t)(bh * DHV + row) * TV + tk0 + (colb >> 1);
            cp16(sb + AVH + sw, g_vth + gv);
            cp16(sb + AVL + sw, g_vtl + gv);
        }
        cp_commit();
    };

    // ---- preload: q (group), k0 (group), v0 (group) ----
#pragma unroll
    for (int it = 0; it < 4; ++it) {
        const int idx = it * 128 + tid;
        const int row = idx >> 3;
        const int colb = (idx & 7) * 16;
        const uint32_t sw = (uint32_t)(row * 128 + (colb ^ ((row & 7) << 4)));
        const size_t gq = (size_t)(b * TV + tq0 + row) * CV + h * DHV + (colb >> 1);
        cp16(sb + AQH + sw, g_qh + gq);
        cp16(sb + AQL + sw, g_ql + gq);
    }
    cp_commit();
    issueK(0);
    issueV(0);

    cp_wait1();          // q + k0 complete for self (v0 may be pending)
    __syncthreads();     // q + k0 visible to all threads

    // persistent q fragments
    uint32_t qfh[4][4], qfl[4][4];
    {
        const int ar = w * 16 + (lane & 15);
        const int ak = ((lane >> 4) & 1) * 16;
#pragma unroll
        for (int ks = 0; ks < 4; ++ks) {
            const uint32_t ad = sb + (uint32_t)(ar * 128 + ((ks * 32 + ak) ^ ((ar & 7) << 4)));
            ldsm4(qfh[ks][0], qfh[ks][1], qfh[ks][2], qfh[ks][3], ad + AQH);
            ldsm4(qfl[ks][0], qfl[ks][1], qfl[ks][2], qfl[ks][3], ad + AQL);
        }
    }

    float o[8][4];
#pragma unroll
    for (int nb = 0; nb < 8; ++nb)
#pragma unroll
        for (int e = 0; e < 4; ++e) o[nb][e] = 0.f;

    const int b_row = (lane & 7) + ((lane >> 4) & 1) * 8;
    const int b_koffb = ((lane >> 3) & 1) * 16;

    for (int kt = 0; kt <= qt; ++kt) {
        const int tk0 = kt * 64;

        // ---- S = q k^T (3-term hi/lo); k(kt) visible ----
        float s[8][4];
#pragma unroll
        for (int nb = 0; nb < 8; ++nb)
#pragma unroll
            for (int e = 0; e < 4; ++e) s[nb][e] = 0.f;

#pragma unroll
        for (int ks = 0; ks < 4; ++ks) {
#pragma unroll
            for (int nq = 0; nq < 4; ++nq) {
                const int r = nq * 16 + b_row;
                const uint32_t bd = sb + (uint32_t)(r * 128 +
                                     ((ks * 32 + b_koffb) ^ ((r & 7) << 4)));
                uint32_t h0, h1, h2, h3, l0, l1, l2, l3;
                ldsm4(h0, h1, h2, h3, bd + AKH);
                ldsm4(l0, l1, l2, l3, bd + AKL);
                uint32_t bh0[2] = {h0, h1}, bh1[2] = {h2, h3};
                uint32_t bl0[2] = {l0, l1}, bl1[2] = {l2, l3};
                mma_bf16(s[nq * 2],     qfh[ks], bh0);
                mma_bf16(s[nq * 2],     qfh[ks], bl0);
                mma_bf16(s[nq * 2],     qfl[ks], bh0);
                mma_bf16(s[nq * 2 + 1], qfh[ks], bh1);
                mma_bf16(s[nq * 2 + 1], qfh[ks], bl1);
                mma_bf16(s[nq * 2 + 1], qfl[ks], bh1);
            }
        }

        // all warps done reading k smem; overwrite it with k(kt+1)
        __syncthreads();
        if (kt < qt) { issueK(kt + 1); cp_wait1(); }   // v(kt) done for self
        else         { cp_wait0(); }                   // v(kt) done for self
        __syncthreads();   // v(kt) visible to ALL threads (race fix vs R11)

        // ---- decay * scale ----
        const int dbase = tq0 - tk0;
        const float rf0 = 0.125f * fast_exp2((float)(dbase + w * 16 + g) * l2g);
        const float rf8 = rf0 * gpow8;
        float cf = ctf;
        if (kt < qt) {
#pragma unroll
            for (int nb = 0; nb < 8; ++nb) {
                const float c0f = cf, c1f = cf * ginv1;
                s[nb][0] *= rf0 * c0f;
                s[nb][1] *= rf0 * c1f;
                s[nb][2] *= rf8 * c0f;
                s[nb][3] *= rf8 * c1f;
                cf *= ginv8;
            }
        } else {
            const int r0 = w * 16 + g, r1 = r0 + 8;
#pragma unroll
            for (int nb = 0; nb < 8; ++nb) {
                const int j0 = 8 * nb + 2 * t4;
                const float c0f = cf, c1f = cf * ginv1;
                s[nb][0] = (r0 >= j0)     ? s[nb][0] * rf0 * c0f : 0.f;
                s[nb][1] = (r0 >= j0 + 1) ? s[nb][1] * rf0 * c1f : 0.f;
                s[nb][2] = (r1 >= j0)     ? s[nb][2] * rf8 * c0f : 0.f;
                s[nb][3] = (r1 >= j0 + 1) ? s[nb][3] * rf8 * c1f : 0.f;
                cf *= ginv8;
            }
        }

        // ---- S -> bf16 hi/lo A-fragments ----
        uint32_t sah[4][4], sal[4][4];
#pragma unroll
        for (int kc = 0; kc < 4; ++kc) {
            const int n0 = 2 * kc, n1 = 2 * kc + 1;
            uint32_t p;
            p = pack_bf16(s[n0][0], s[n0][1]);
            sah[kc][0] = p;
            sal[kc][0] = pack_bf16(s[n0][0] - bf16lo_f32(p), s[n0][1] - bf16hi_f32(p));
            p = pack_bf16(s[n0][2], s[n0][3]);
            sah[kc][1] = p;
            sal[kc][1] = pack_bf16(s[n0][2] - bf16lo_f32(p), s[n0][3] - bf16hi_f32(p));
            p = pack_bf16(s[n1][0], s[n1][1]);
            sah[kc][2] = p;
            sal[kc][2] = pack_bf16(s[n1][0] - bf16lo_f32(p), s[n1][1] - bf16hi_f32(p));
            p = pack_bf16(s[n1][2], s[n1][3]);
            sah[kc][3] = p;
            sal[kc][3] = pack_bf16(s[n1][2] - bf16lo_f32(p), s[n1][3] - bf16hi_f32(p));
        }

        // ---- O += S v (3-term hi/lo); v(kt) visible ----
#pragma unroll
        for (int kc = 0; kc < 4; ++kc) {
#pragma unroll
            for (int nq = 0; nq < 4; ++nq) {
                const int r = nq * 16 + b_row;
                const uint32_t bd = sb + (uint32_t)(r * 128 +
                                     ((kc * 32 + b_koffb) ^ ((r & 7) << 4)));
                uint32_t h0, h1, h2, h3, l0, l1, l2, l3;
                ldsm4(h0, h1, h2, h3, bd + AVH);
                ldsm4(l0, l1, l2, l3, bd + AVL);
                uint32_t vh0[2] = {h0, h1}, vh1[2] = {h2, h3};
                uint32_t vl0[2] = {l0, l1}, vl1[2] = {l2, l3};
                mma_bf16(o[nq * 2],     sah[kc], vh0);
                mma_bf16(o[nq * 2],     sah[kc], vl0);
                mma_bf16(o[nq * 2],     sal[kc], vh0);
                mma_bf16(o[nq * 2 + 1], sah[kc], vh1);
                mma_bf16(o[nq * 2 + 1], sah[kc], vl1);
                mma_bf16(o[nq * 2 + 1], sal[kc], vh1);
            }
        }

        // all warps done reading v smem; overwrite it with v(kt+1)
        __syncthreads();
        if (kt < qt) {
            issueV(kt + 1);
            cp_wait1();        // k(kt+1) done for self
            __syncthreads();   // k(kt+1) visible to ALL threads (race fix vs R11)
        }
    }

    // ---- fused GroupNorm + bf16 hi/lo store into out-proj input ----
    float sum0 = 0.f, sq0 = 0.f, sum1 = 0.f, sq1 = 0.f;
#pragma unroll
    for (int nb = 0; nb < 8; ++nb) {
        sum0 += o[nb][0] + o[nb][1];
        sq0  += o[nb][0] * o[nb][0] + o[nb][1] * o[nb][1];
        sum1 += o[nb][2] + o[nb][3];
        sq1  += o[nb][2] * o[nb][2] + o[nb][3] * o[nb][3];
    }
#pragma unroll
    for (int off = 1; off < 4; off <<= 1) {
        sum0 += __shfl_xor_sync(0xffffffffu, sum0, off);
        sq0  += __shfl_xor_sync(0xffffffffu, sq0,  off);
        sum1 += __shfl_xor_sync(0xffffffffu, sum1, off);
        sq1  += __shfl_xor_sync(0xffffffffu, sq1,  off);
    }
    const float invn = 1.0f / 64.0f;
    const float mean0 = sum0 * invn;
    const float mean1 = sum1 * invn;
    const float rs0 = rsqrtf(sq0 * invn - mean0 * mean0 + 1e-5f);
    const float rs1 = rsqrtf(sq1 * invn - mean1 * mean1 + 1e-5f);

    const int row0 = tq0 + w * 16 + g;
    const size_t base0 = (size_t)(b * TV + row0) * CV + h * DHV;
    const size_t base1 = base0 + (size_t)8 * CV;

#pragma unroll
    for (int nb = 0; nb < 8; ++nb) {
        const int d0 = 8 * nb + 2 * t4;
        const float2 wv = *(const float2*)(gn_w + h * DHV + d0);
        const float2 bv = *(const float2*)(gn_b + h * DHV + d0);
        float y00 = (o[nb][0] - mean0) * rs0 * wv.x + bv.x;
        float y01 = (o[nb][1] - mean0) * rs0 * wv.y + bv.y;
        float y10 = (o[nb][2] - mean1) * rs1 * wv.x + bv.x;
        float y11 = (o[nb][3] - mean1) * rs1 * wv.y + bv.y;

        uint32_t p0 = pack_bf16(y00, y01);
        uint32_t q0 = pack_bf16(y00 - bf16lo_f32(p0), y01 - bf16hi_f32(p0));
        uint32_t p1 = pack_bf16(y10, y11);
        uint32_t q1 = pack_bf16(y10 - bf16lo_f32(p1), y11 - bf16hi_f32(p1));

        *(uint32_t*)(g_xh + base0 + d0) = p0;
        *(uint32_t*)(g_xl + base0 + d0) = q0;
        *(uint32_t*)(g_xh + base1 + d0) = p1;
        *(uint32_t*)(g_xl + base1 + d0) = q1;
    }
}

// ---------------------------------------------------------------------------
extern "C" void kernel_launch(void* const* d_in, const int* in_sizes, int n_in,
                              void* d_out, int out_size)
{
    const float* x   = (const float*)d_in[0];
    const float* Wq  = (const float*)d_in[1];
    const float* Wk  = (const float*)d_in[2];
    const float* Wv  = (const float*)d_in[3];
    const float* Wo  = (const float*)d_in[4];
    const float* gnw = (const float*)d_in[5];
    const float* gnb = (const float*)d_in[6];
    float* out = (float*)d_out;

    float *q, *k, *v;
    __nv_bfloat16 *xh, *xl, *wh, *wl, *woh, *wol;
    cudaGetSymbolAddress((void**)&q, g_q);
    cudaGetSymbolAddress((void**)&k, g_k);
    cudaGetSymbolAddress((void**)&v, g_v);
    cudaGetSymbolAddress((void**)&xh, g_xh);
    cudaGetSymbolAddress((void**)&xl, g_xl);
    cudaGetSymbolAddress((void**)&wh, g_wh);
    cudaGetSymbolAddress((void**)&wl, g_wl);
    cudaGetSymbolAddress((void**)&woh, g_woh);
    cudaGetSymbolAddress((void**)&wol, g_wol);

    cudaFuncSetAttribute(bfgemm,
                         cudaFuncAttributeMaxDynamicSharedMemorySize, GEMM_SMEM);
    cudaFuncSetAttribute(retention_mma,
                         cudaFuncAttributeMaxDynamicSharedMemorySize, ATTN_SMEM);

    const int WN4 = CV * CV / 4;
    const int XN4 = MV * CV / 4;

    // 0) hi/lo bf16 splits of inputs
    conv_hilo<<<XN4 / 256, 256>>>(x, xh, xl, XN4);
    conv_hilo<<<WN4 / 256, 256>>>(Wq, wh,                       wl,                       WN4);
    conv_hilo<<<WN4 / 256, 256>>>(Wk, wh + (size_t)CV * CV,     wl + (size_t)CV * CV,     WN4);
    conv_hilo<<<WN4 / 256, 256>>>(Wv, wh + (size_t)2 * CV * CV, wl + (size_t)2 * CV * CV, WN4);
    conv_hilo<<<WN4 / 256, 256>>>(Wo, woh, wol, WN4);

    // 1) QKV projections (tensor cores)
    bfgemm<<<dim3(CV / 128, MV / 128, 3), 256, GEMM_SMEM>>>(xh, xl, wh, wl, q, k, v);
    // 2) RoPE + bf16 hi/lo q,k
    rope_conv<<<(BV * TV * HV * 32) / 256, 256>>>();
    // 3) v transpose + hi/lo
    vtrans<<<dim3(TV / 64, BV * HV), 256>>>();
    // 4) Retention on tensor cores + fused GroupNorm -> g_xh/g_xl
    retention_mma<<<dim3(TV / 64, BV * HV), 128, ATTN_SMEM>>>(gnw, gnb);
    // 5) Output projection (tensor cores)
    bfgemm<<<dim3(CV / 128, MV / 128, 1), 256, GEMM_SMEM>>>(xh, xl, woh, wol, out, out, out);
}

// round 15
// speedup vs baseline: 1.2435x; 1.1971x over previous
#include <cuda_runtime.h>
#include <cuda_bf16.h>
#include <cuda_fp16.h>
#include <math.h>
#include <stdint.h>

#define BV 2
#define TV 2048
#define CV 1024
#define HV 16
#define DHV 64
#define MV (BV * TV)   // 4096

// ---------------------------------------------------------------------------
// Scratch (__device__ globals; allocation-free rule)
// ---------------------------------------------------------------------------
__device__ float g_q[(size_t)MV * CV];
__device__ float g_k[(size_t)MV * CV];
__device__ float g_v[(size_t)MV * CV];

__device__ __half g_xh[(size_t)MV * CV];          // fp16 x (then normed y) single limb
__device__ __half g_wh[(size_t)3 * CV * CV];      // Wq,Wk,Wv hi limb (fp16)
__device__ __half g_wl[(size_t)3 * CV * CV];      // Wq,Wk,Wv lo limb (fp16)
__device__ __half g_woh[(size_t)CV * CV];         // Wo hi
__device__ __half g_wol[(size_t)CV * CV];         // Wo lo

__device__ __nv_bfloat16 g_qh[(size_t)MV * CV];   // roped q hi/lo (bf16) [b*T+t][h*64+d]
__device__ __nv_bfloat16 g_ql[(size_t)MV * CV];
__device__ __nv_bfloat16 g_kh[(size_t)MV * CV];   // roped k hi/lo
__device__ __nv_bfloat16 g_kl[(size_t)MV * CV];
__device__ __nv_bfloat16 g_vth[(size_t)MV * CV];  // v^T hi/lo  [bh][d][t]
__device__ __nv_bfloat16 g_vtl[(size_t)MV * CV];

// ---------------------------------------------------------------------------
// helpers
// ---------------------------------------------------------------------------
__device__ __forceinline__ uint32_t smem_to_u32(const void* p) {
    uint32_t a;
    asm("{ .reg .u64 t; cvta.to.shared.u64 t, %1; cvt.u32.u64 %0, t; }"
        : "=r"(a) : "l"(p));
    return a;
}
__device__ __forceinline__ void cp16(uint32_t saddr, const void* g) {
    asm volatile("cp.async.cg.shared.global [%0], [%1], 16;"
                 :: "r"(saddr), "l"(g) : "memory");
}
__device__ __forceinline__ void cp_commit() {
    asm volatile("cp.async.commit_group;" ::: "memory");
}
__device__ __forceinline__ void cp_wait1() {
    asm volatile("cp.async.wait_group 1;" ::: "memory");
}
__device__ __forceinline__ void cp_wait0() {
    asm volatile("cp.async.wait_group 0;" ::: "memory");
}
__device__ __forceinline__ void ldsm4(uint32_t& r0, uint32_t& r1,
                                      uint32_t& r2, uint32_t& r3, uint32_t addr) {
    asm volatile("ldmatrix.sync.aligned.m8n8.x4.shared.b16 {%0,%1,%2,%3}, [%4];"
                 : "=r"(r0), "=r"(r1), "=r"(r2), "=r"(r3) : "r"(addr));
}
__device__ __forceinline__ void mma_bf16(float* c, const uint32_t* a, const uint32_t* b) {
    asm volatile(
        "mma.sync.aligned.m16n8k16.row.col.f32.bf16.bf16.f32 "
        "{%0,%1,%2,%3}, {%4,%5,%6,%7}, {%8,%9}, {%0,%1,%2,%3};"
        : "+f"(c[0]), "+f"(c[1]), "+f"(c[2]), "+f"(c[3])
        : "r"(a[0]), "r"(a[1]), "r"(a[2]), "r"(a[3]), "r"(b[0]), "r"(b[1]));
}
__device__ __forceinline__ void mma_f16(float* c, const uint32_t* a, const uint32_t* b) {
    asm volatile(
        "mma.sync.aligned.m16n8k16.row.col.f32.f16.f16.f32 "
        "{%0,%1,%2,%3}, {%4,%5,%6,%7}, {%8,%9}, {%0,%1,%2,%3};"
        : "+f"(c[0]), "+f"(c[1]), "+f"(c[2]), "+f"(c[3])
        : "r"(a[0]), "r"(a[1]), "r"(a[2]), "r"(a[3]), "r"(b[0]), "r"(b[1]));
}
__device__ __forceinline__ float fast_exp2(float x) {
    float r;
    asm("ex2.approx.f32 %0, %1;" : "=f"(r) : "f"(x));
    return r;
}
// pack: result = {lo, hi} bf16x2
__device__ __forceinline__ uint32_t pack_bf16(float lo, float hi) {
    uint32_t r;
    asm("cvt.rn.bf16x2.f32 %0, %1, %2;" : "=r"(r) : "f"(hi), "f"(lo));
    return r;
}
__device__ __forceinline__ float bf16lo_f32(uint32_t p) { return __uint_as_float(p << 16); }
__device__ __forceinline__ float bf16hi_f32(uint32_t p) { return __uint_as_float(p & 0xffff0000u); }

// ---------------------------------------------------------------------------
// fp32 -> fp16 single limb (vec4)
// ---------------------------------------------------------------------------
__global__ void conv_f16(const float* __restrict__ src, __half* __restrict__ dst, int n4)
{
    int i = blockIdx.x * blockDim.x + threadIdx.x;
    if (i >= n4) return;
    float4 v = ((const float4*)src)[i];
    __half2 a = __floats2half2_rn(v.x, v.y);
    __half2 b = __floats2half2_rn(v.z, v.w);
    ((uint2*)dst)[i] = make_uint2(*(uint32_t*)&a, *(uint32_t*)&b);
}

// ---------------------------------------------------------------------------
// fp32 -> (fp16 hi, fp16 lo) two-limb split (vec4)
// ---------------------------------------------------------------------------
__global__ void conv_f16_2(const float* __restrict__ src,
                           __half* __restrict__ hi, __half* __restrict__ lo, int n4)
{
    int i = blockIdx.x * blockDim.x + threadIdx.x;
    if (i >= n4) return;
    float4 v = ((const float4*)src)[i];
    __half h0 = __float2half_rn(v.x);
    __half h1 = __float2half_rn(v.y);
    __half h2 = __float2half_rn(v.z);
    __half h3 = __float2half_rn(v.w);
    __half l0 = __float2half_rn(v.x - __half2float(h0));
    __half l1 = __float2half_rn(v.y - __half2float(h1));
    __half l2 = __float2half_rn(v.z - __half2float(h2));
    __half l3 = __float2half_rn(v.w - __half2float(h3));
    __half2 hA = __halves2half2(h0, h1), hB = __halves2half2(h2, h3);
    __half2 lA = __halves2half2(l0, l1), lB = __halves2half2(l2, l3);
    ((uint2*)hi)[i] = make_uint2(*(uint32_t*)&hA, *(uint32_t*)&hB);
    ((uint2*)lo)[i] = make_uint2(*(uint32_t*)&lA, *(uint32_t*)&lB);
}

// ---------------------------------------------------------------------------
// Warp-MMA fp16 GEMM, 2-product emulation: C = fp16(A) @ (Wh + Wl)^T.
// Dropped term (A - fp16(A))·W gives rel err ~2.8e-4 per GEMM.
// CTA 128x128, K-chunk 64, 8 warps (4m x 2n), double-buffered cp.async.
// SMEM per stage: A 16KB + Bh 16KB + Bl 16KB = 48KB; 2 stages = 96KB.
// ---------------------------------------------------------------------------
#define STAGE_BYTES 49152
#define OFF_A  0
#define OFF_BH 16384
#define OFF_BL 32768
#define GEMM_SMEM (2 * STAGE_BYTES)

__global__ __launch_bounds__(256)
void hgemm2(const __half* __restrict__ Ah,
            const __half* __restrict__ Wh0,
            const __half* __restrict__ Wl0,
            float* __restrict__ C0, float* __restrict__ C1, float* __restrict__ C2)
{
    extern __shared__ char smem[];
    const uint32_t sb = smem_to_u32(smem);
    const int tid = threadIdx.x;
    const int wid = tid >> 5;
    const int lane = tid & 31;
    const int z = blockIdx.z;

    const __half* Wh = Wh0 + (size_t)z * CV * CV;
    const __half* Wl = Wl0 + (size_t)z * CV * CV;
    float* C = (z == 0) ? C0 : ((z == 1) ? C1 : C2);

    const int bm = blockIdx.y * 128;
    const int bn = blockIdx.x * 128;
    const int warp_m = wid >> 1;
    const int warp_n = wid & 1;

    float c[2][8][4];
#pragma unroll
    for (int mb = 0; mb < 2; ++mb)
#pragma unroll
        for (int nb = 0; nb < 8; ++nb)
#pragma unroll
            for (int e = 0; e < 4; ++e) c[mb][nb][e] = 0.f;

    auto issue = [&](int ch, int stage) {
        const int kc0 = ch * 64;
        const uint32_t base = sb + stage * STAGE_BYTES;
#pragma unroll
        for (int it = 0; it < 4; ++it) {
            const int idx = it * 256 + tid;
            const int row = idx >> 3;
            const int colb = (idx & 7) * 16;
            const uint32_t sw = (uint32_t)(row * 128 + (colb ^ ((row & 7) << 4)));
            const size_t gA = (size_t)(bm + row) * CV + kc0 + (colb >> 1);
            const size_t gB = (size_t)(bn + row) * CV + kc0 + (colb >> 1);
            cp16(base + OFF_A + sw, Ah + gA);
            cp16(base + OFF_BH + sw, Wh + gB);
            cp16(base + OFF_BL + sw, Wl + gB);
        }
        cp_commit();
    };

    issue(0, 0);

    const int a_row16 = lane & 15;
    const int a_koffb = ((lane >> 4) & 1) * 16;
    const int b_rowsel = (lane & 7) + ((lane >> 4) & 1) * 8;
    const int b_koffb = ((lane >> 3) & 1) * 16;

    const int NT = 16;
    for (int ch = 0; ch < NT; ++ch) {
        if (ch + 1 < NT) issue(ch + 1, (ch + 1) & 1);
        if (ch + 1 < NT) cp_wait1(); else cp_wait0();
        __syncthreads();

        const uint32_t base = sb + (ch & 1) * STAGE_BYTES;
#pragma unroll
        for (int ks = 0; ks < 4; ++ks) {
            const int kb = ks * 32;

            uint32_t ah[2][4];
#pragma unroll
            for (int mb = 0; mb < 2; ++mb) {
                const int r = warp_m * 32 + mb * 16 + a_row16;
                const uint32_t ad = base + (uint32_t)(r * 128 +
                                     ((kb + a_koffb) ^ ((r & 7) << 4)));
                ldsm4(ah[mb][0], ah[mb][1], ah[mb][2], ah[mb][3], ad + OFF_A);
            }

            uint32_t bh[8][2], bl[8][2];
#pragma unroll
            for (int nq = 0; nq < 4; ++nq) {
                const int r = warp_n * 64 + nq * 16 + b_rowsel;
                const uint32_t bd = base + (uint32_t)(r * 128 +
                                     ((kb + b_koffb) ^ ((r & 7) << 4)));
                uint32_t t0, t1, t2, t3;
                ldsm4(t0, t1, t2, t3, bd + OFF_BH);
                bh[nq * 2][0] = t0; bh[nq * 2][1] = t1;
                bh[nq * 2 + 1][0] = t2; bh[nq * 2 + 1][1] = t3;
                ldsm4(t0, t1, t2, t3, bd + OFF_BL);
                bl[nq * 2][0] = t0; bl[nq * 2][1] = t1;
                bl[nq * 2 + 1][0] = t2; bl[nq * 2 + 1][1] = t3;
            }

#pragma unroll
            for (int mb = 0; mb < 2; ++mb)
#pragma unroll
                for (int nb = 0; nb < 8; ++nb) {
                    mma_f16(c[mb][nb], ah[mb], bh[nb]);
                    mma_f16(c[mb][nb], ah[mb], bl[nb]);
                }
        }
        __syncthreads();
    }

    const int gr = lane >> 2;
    const int gc = (lane & 3) * 2;
#pragma unroll
    for (int mb = 0; mb < 2; ++mb) {
        const int row0 = bm + warp_m * 32 + mb * 16 + gr;
#pragma unroll
        for (int nb = 0; nb < 8; ++nb) {
            const int col = bn + warp_n * 64 + nb * 8 + gc;
            *(float2*)(C + (size_t)row0 * CV + col) =
                make_float2(c[mb][nb][0], c[mb][nb][1]);
            *(float2*)(C + (size_t)(row0 + 8) * CV + col) =
                make_float2(c[mb][nb][2], c[mb][nb][3]);
        }
    }
}

// ---------------------------------------------------------------------------
// RoPE on q and k + bf16 hi/lo conversion. Thread per (b,t,h,j<32).
// ---------------------------------------------------------------------------
__global__ void rope_conv()
{
    const int idx = blockIdx.x * blockDim.x + threadIdx.x;
    const int j = idx & 31;
    const int h = (idx >> 5) & (HV - 1);
    const int t = (idx >> 9) & (TV - 1);
    const int b = idx >> 20;

    const float L2_10000 = 13.287712379549449f;
    const float invf = exp2f(-(float)j * (L2_10000 / 32.0f));
    const float ang = (float)t * invf;
    float sn, cs;
    sincosf(ang, &sn, &cs);

    const size_t base = (size_t)(b * TV + t) * CV + h * DHV + j;

    float q1 = g_q[base], q2 = g_q[base + 32];
    float qa = q1 * cs - q2 * sn;
    float qb = q2 * cs + q1 * sn;
    float k1 = g_k[base], k2 = g_k[base + 32];
    float ka = k1 * cs - k2 * sn;
    float kb = k2 * cs + k1 * sn;

    __nv_bfloat16 hqa = __float2bfloat16(qa);
    __nv_bfloat16 hqb = __float2bfloat16(qb);
    __nv_bfloat16 hka = __float2bfloat16(ka);
    __nv_bfloat16 hkb = __float2bfloat16(kb);
    g_qh[base]      = hqa;
    g_qh[base + 32] = hqb;
    g_ql[base]      = __float2bfloat16(qa - __bfloat162float(hqa));
    g_ql[base + 32] = __float2bfloat16(qb - __bfloat162float(hqb));
    g_kh[base]      = hka;
    g_kh[base + 32] = hkb;
    g_kl[base]      = __float2bfloat16(ka - __bfloat162float(hka));
    g_kl[base + 32] = __float2bfloat16(kb - __bfloat162float(hkb));
}

// ---------------------------------------------------------------------------
// v transpose + hi/lo: g_v [b*T+t][h*64+d] -> g_vth/g_vtl [bh][d][t].
// ---------------------------------------------------------------------------
__global__ __launch_bounds__(256)
void vtrans()
{
    __shared__ float vt[64][65];
    const int bh = blockIdx.y;
    const int b = bh >> 4, h = bh & 15;
    const int t0 = blockIdx.x * 64;
    const int tid = threadIdx.x;

#pragma unroll
    for (int it = 0; it < 4; ++it) {
        const int idx = it * 256 + tid;
        const int row = idx >> 4;
        const int c4 = (idx & 15) * 4;
        float4 v = *(const float4*)(g_v + (size_t)(b * TV + t0 + row) * CV + h * DHV + c4);
        vt[row][c4 + 0] = v.x; vt[row][c4 + 1] = v.y;
        vt[row][c4 + 2] = v.z; vt[row][c4 + 3] = v.w;
    }
    __syncthreads();

#pragma unroll
    for (int it = 0; it < 4; ++it) {
        const int idx = it * 256 + tid;
        const int d = idx >> 4;
        const int tc = (idx & 15) * 4;
        float x0 = vt[tc + 0][d], x1 = vt[tc + 1][d];
        float x2 = vt[tc + 2][d], x3 = vt[tc + 3][d];
        uint32_t h01 = pack_bf16(x0, x1);
        uint32_t h23 = pack_bf16(x2, x3);
        float r0 = x0 - bf16lo_f32(h01), r1 = x1 - bf16hi_f32(h01);
        float r2 = x2 - bf16lo_f32(h23), r3 = x3 - bf16hi_f32(h23);
        uint32_t l01 = pack_bf16(r0, r1);
        uint32_t l23 = pack_bf16(r2, r3);
        const size_t off = (size_t)(bh * DHV + d) * TV + t0 + tc;
        *(uint2*)(g_vth + off) = make_uint2(h01, h23);
        *(uint2*)(g_vtl + off) = make_uint2(l01, l23);
    }
}

// ---------------------------------------------------------------------------
// Retention attention on tensor cores (R12 PASS version, unchanged math)
// except the epilogue now writes a single fp16 limb into g_xh (out-proj A).
// ---------------------------------------------------------------------------
#define AQH 0
#define AQL 8192
#define AKH 16384
#define AKL 24576
#define AVH 32768
#define AVL 40960
#define ATTN_SMEM 49152

__global__ __launch_bounds__(128)
void retention_mma(const float* __restrict__ gn_w, const float* __restrict__ gn_b)
{
    extern __shared__ char smem[];
    const uint32_t sb = smem_to_u32(smem);
    const int tid = threadIdx.x;
    const int w = tid >> 5;
    const int lane = tid & 31;

    const int qt = (int)(gridDim.x - 1 - blockIdx.x);   // big tiles first
    const int bh = blockIdx.y;
    const int b = bh >> 4, h = bh & 15;
    const int tq0 = qt * 64;

    const int g = lane >> 2;
    const int t4 = lane & 3;

    const float gamma = 1.0f - __int_as_float((127 - 5 - h) << 23);
    const float l2g = log2f(gamma);
    const float ginv1 = fast_exp2(-l2g);
    const float ginv8 = fast_exp2(-8.0f * l2g);
    const float gpow8 = fast_exp2(8.0f * l2g);
    const float ctf = fast_exp2(-2.0f * (float)t4 * l2g);

    auto issueK = [&](int kt) {
        const int tk0 = kt * 64;
#pragma unroll
        for (int it = 0; it < 4; ++it) {
            const int idx = it * 128 + tid;
            const int row = idx >> 3;
            const int colb = (idx & 7) * 16;
            const uint32_t sw = (uint32_t)(row * 128 + (colb ^ ((row & 7) << 4)));
            const size_t gk = (size_t)(b * TV + tk0 + row) * CV + h * DHV + (colb >> 1);
            cp16(sb + AKH + sw, g_kh + gk);
            cp16(sb + AKL + sw, g_kl + gk);
        }
        cp_commit();
    };
    auto issueV = [&](int kt) {
        const int tk0 = kt * 64;
#pragma unroll
        for (int it = 0; it < 4; ++it) {
            const int idx = it * 128 + tid;
            const int row = idx >> 3;
            const int colb = (idx & 7) * 16;
            const uint32_t sw = (uint32_t)(row * 128 + (colb ^ ((row & 7) << 4)));
            const size_t gv = (size_t)(bh * DHV + row) * TV + tk0 + (colb >> 1);
            cp16(sb + AVH + sw, g_vth + gv);
            cp16(sb + AVL + sw, g_vtl + gv);
        }
        cp_commit();
    };

#pragma unroll
    for (int it = 0; it < 4; ++it) {
        const int idx = it * 128 + tid;
        const int row = idx >> 3;
        const int colb = (idx & 7) * 16;
        const uint32_t sw = (uint32_t)(row * 128 + (colb ^ ((row & 7) << 4)));
        const size_t gq = (size_t)(b * TV + tq0 + row) * CV + h * DHV + (colb >> 1);
        cp16(sb + AQH + sw, g_qh + gq);
        cp16(sb + AQL + sw, g_ql + gq);
    }
    cp_commit();
    issueK(0);
    issueV(0);

    cp_wait1();
    __syncthreads();

    uint32_t qfh[4][4], qfl[4][4];
    {
        const int ar = w * 16 + (lane & 15);
        const int ak = ((lane >> 4) & 1) * 16;
#pragma unroll
        for (int ks = 0; ks < 4; ++ks) {
            const uint32_t ad = sb + (uint32_t)(ar * 128 + ((ks * 32 + ak) ^ ((ar & 7) << 4)));
            ldsm4(qfh[ks][0], qfh[ks][1], qfh[ks][2], qfh[ks][3], ad + AQH);
            ldsm4(qfl[ks][0], qfl[ks][1], qfl[ks][2], qfl[ks][3], ad + AQL);
        }
    }

    float o[8][4];
#pragma unroll
    for (int nb = 0; nb < 8; ++nb)
#pragma unroll
        for (int e = 0; e < 4; ++e) o[nb][e] = 0.f;

    const int b_row = (lane & 7) + ((lane >> 4) & 1) * 8;
    const int b_koffb = ((lane >> 3) & 1) * 16;

    for (int kt = 0; kt <= qt; ++kt) {
        const int tk0 = kt * 64;

        float s[8][4];
#pragma unroll
        for (int nb = 0; nb < 8; ++nb)
#pragma unroll
            for (int e = 0; e < 4; ++e) s[nb][e] = 0.f;

#pragma unroll
        for (int ks = 0; ks < 4; ++ks) {
#pragma unroll
            for (int nq = 0; nq < 4; ++nq) {
                const int r = nq * 16 + b_row;
                const uint32_t bd = sb + (uint32_t)(r * 128 +
                                     ((ks * 32 + b_koffb) ^ ((r & 7) << 4)));
                uint32_t h0, h1, h2, h3, l0, l1, l2, l3;
                ldsm4(h0, h1, h2, h3, bd + AKH);
                ldsm4(l0, l1, l2, l3, bd + AKL);
                uint32_t bh0[2] = {h0, h1}, bh1[2] = {h2, h3};
                uint32_t bl0[2] = {l0, l1}, bl1[2] = {l2, l3};
                mma_bf16(s[nq * 2],     qfh[ks], bh0);
                mma_bf16(s[nq * 2],     qfh[ks], bl0);
                mma_bf16(s[nq * 2],     qfl[ks], bh0);
                mma_bf16(s[nq * 2 + 1], qfh[ks], bh1);
                mma_bf16(s[nq * 2 + 1], qfh[ks], bl1);
                mma_bf16(s[nq * 2 + 1], qfl[ks], bh1);
            }
        }

        __syncthreads();
        if (kt < qt) { issueK(kt + 1); cp_wait1(); }
        else         { cp_wait0(); }
        __syncthreads();   // v(kt) visible to ALL threads

        const int dbase = tq0 - tk0;
        const float rf0 = 0.125f * fast_exp2((float)(dbase + w * 16 + g) * l2g);
        const float rf8 = rf0 * gpow8;
        float cf = ctf;
        if (kt < qt) {
#pragma unroll
            for (int nb = 0; nb < 8; ++nb) {
                const float c0f = cf, c1f = cf * ginv1;
                s[nb][0] *= rf0 * c0f;
                s[nb][1] *= rf0 * c1f;
                s[nb][2] *= rf8 * c0f;
                s[nb][3] *= rf8 * c1f;
                cf *= ginv8;
            }
        } else {
            const int r0 = w * 16 + g, r1 = r0 + 8;
#pragma unroll
            for (int nb = 0; nb < 8; ++nb) {
                const int j0 = 8 * nb + 2 * t4;
                const float c0f = cf, c1f = cf * ginv1;
                s[nb][0] = (r0 >= j0)     ? s[nb][0] * rf0 * c0f : 0.f;
                s[nb][1] = (r0 >= j0 + 1) ? s[nb][1] * rf0 * c1f : 0.f;
                s[nb][2] = (r1 >= j0)     ? s[nb][2] * rf8 * c0f : 0.f;
                s[nb][3] = (r1 >= j0 + 1) ? s[nb][3] * rf8 * c1f : 0.f;
                cf *= ginv8;
            }
        }

        uint32_t sah[4][4], sal[4][4];
#pragma unroll
        for (int kc = 0; kc < 4; ++kc) {
            const int n0 = 2 * kc, n1 = 2 * kc + 1;
            uint32_t p;
            p = pack_bf16(s[n0][0], s[n0][1]);
            sah[kc][0] = p;
            sal[kc][0] = pack_bf16(s[n0][0] - bf16lo_f32(p), s[n0][1] - bf16hi_f32(p));
            p = pack_bf16(s[n0][2], s[n0][3]);
            sah[kc][1] = p;
            sal[kc][1] = pack_bf16(s[n0][2] - bf16lo_f32(p), s[n0][3] - bf16hi_f32(p));
            p = pack_bf16(s[n1][0], s[n1][1]);
            sah[kc][2] = p;
            sal[kc][2] = pack_bf16(s[n1][0] - bf16lo_f32(p), s[n1][1] - bf16hi_f32(p));
            p = pack_bf16(s[n1][2], s[n1][3]);
            sah[kc][3] = p;
            sal[kc][3] = pack_bf16(s[n1][2] - bf16lo_f32(p), s[n1][3] - bf16hi_f32(p));
        }

#pragma unroll
        for (int kc = 0; kc < 4; ++kc) {
#pragma unroll
            for (int nq = 0; nq < 4; ++nq) {
                const int r = nq * 16 + b_row;
                const uint32_t bd = sb + (uint32_t)(r * 128 +
                                     ((kc * 32 + b_koffb) ^ ((r & 7) << 4)));
                uint32_t h0, h1, h2, h3, l0, l1, l2, l3;
                ldsm4(h0, h1, h2, h3, bd + AVH);
                ldsm4(l0, l1, l2, l3, bd + AVL);
                uint32_t vh0[2] = {h0, h1}, vh1[2] = {h2, h3};
                uint32_t vl0[2] = {l0, l1}, vl1[2] = {l2, l3};
                mma_bf16(o[nq * 2],     sah[kc], vh0);
                mma_bf16(o[nq * 2],     sah[kc], vl0);
                mma_bf16(o[nq * 2],     sal[kc], vh0);
                mma_bf16(o[nq * 2 + 1], sah[kc], vh1);
                mma_bf16(o[nq * 2 + 1], sah[kc], vl1);
                mma_bf16(o[nq * 2 + 1], sal[kc], vh1);
            }
        }

        __syncthreads();
        if (kt < qt) {
            issueV(kt + 1);
            cp_wait1();
            __syncthreads();   // k(kt+1) visible to ALL threads
        }
    }

    // ---- fused GroupNorm + fp16 store into out-proj input (single limb) ----
    float sum0 = 0.f, sq0 = 0.f, sum1 = 0.f, sq1 = 0.f;
#pragma unroll
    for (int nb = 0; nb < 8; ++nb) {
        sum0 += o[nb][0] + o[nb][1];
        sq0  += o[nb][0] * o[nb][0] + o[nb][1] * o[nb][1];
        sum1 += o[nb][2] + o[nb][3];
        sq1  += o[nb][2] * o[nb][2] + o[nb][3] * o[nb][3];
    }
#pragma unroll
    for (int off = 1; off < 4; off <<= 1) {
        sum0 += __shfl_xor_sync(0xffffffffu, sum0, off);
        sq0  += __shfl_xor_sync(0xffffffffu, sq0,  off);
        sum1 += __shfl_xor_sync(0xffffffffu, sum1, off);
        sq1  += __shfl_xor_sync(0xffffffffu, sq1,  off);
    }
    const float invn = 1.0f / 64.0f;
    const float mean0 = sum0 * invn;
    const float mean1 = sum1 * invn;
    const float rs0 = rsqrtf(sq0 * invn - mean0 * mean0 + 1e-5f);
    const float rs1 = rsqrtf(sq1 * invn - mean1 * mean1 + 1e-5f);

    const int row0 = tq0 + w * 16 + g;
    const size_t base0 = (size_t)(b * TV + row0) * CV + h * DHV;
    const size_t base1 = base0 + (size_t)8 * CV;

#pragma unroll
    for (int nb = 0; nb < 8; ++nb) {
        const int d0 = 8 * nb + 2 * t4;
        const float2 wv = *(const float2*)(gn_w + h * DHV + d0);
        const float2 bv = *(const float2*)(gn_b + h * DHV + d0);
        float y00 = (o[nb][0] - mean0) * rs0 * wv.x + bv.x;
        float y01 = (o[nb][1] - mean0) * rs0 * wv.y + bv.y;
        float y10 = (o[nb][2] - mean1) * rs1 * wv.x + bv.x;
        float y11 = (o[nb][3] - mean1) * rs1 * wv.y + bv.y;

        __half2 p0 = __floats2half2_rn(y00, y01);
        __half2 p1 = __floats2half2_rn(y10, y11);
        *(__half2*)(g_xh + base0 + d0) = p0;
        *(__half2*)(g_xh + base1 + d0) = p1;
    }
}

// ---------------------------------------------------------------------------
extern "C" void kernel_launch(void* const* d_in, const int* in_sizes, int n_in,
                              void* d_out, int out_size)
{
    const float* x   = (const float*)d_in[0];
    const float* Wq  = (const float*)d_in[1];
    const float* Wk  = (const float*)d_in[2];
    const float* Wv  = (const float*)d_in[3];
    const float* Wo  = (const float*)d_in[4];
    const float* gnw = (const float*)d_in[5];
    const float* gnb = (const float*)d_in[6];
    float* out = (float*)d_out;

    float *q, *k, *v;
    __half *xh, *wh, *wl, *woh, *wol;
    cudaGetSymbolAddress((void**)&q, g_q);
    cudaGetSymbolAddress((void**)&k, g_k);
    cudaGetSymbolAddress((void**)&v, g_v);
    cudaGetSymbolAddress((void**)&xh, g_xh);
    cudaGetSymbolAddress((void**)&wh, g_wh);
    cudaGetSymbolAddress((void**)&wl, g_wl);
    cudaGetSymbolAddress((void**)&woh, g_woh);
    cudaGetSymbolAddress((void**)&wol, g_wol);

    cudaFuncSetAttribute(hgemm2,
                         cudaFuncAttributeMaxDynamicSharedMemorySize, GEMM_SMEM);
    cudaFuncSetAttribute(retention_mma,
                         cudaFuncAttributeMaxDynamicSharedMemorySize, ATTN_SMEM);

    const int WN4 = CV * CV / 4;
    const int XN4 = MV * CV / 4;

    // 0) fp16 conversions: x single limb; weights two limbs
    conv_f16<<<XN4 / 256, 256>>>(x, xh, XN4);
    conv_f16_2<<<WN4 / 256, 256>>>(Wq, wh,                       wl,                       WN4);
    conv_f16_2<<<WN4 / 256, 256>>>(Wk, wh + (size_t)CV * CV,     wl + (size_t)CV * CV,     WN4);
    conv_f16_2<<<WN4 / 256, 256>>>(Wv, wh + (size_t)2 * CV * CV, wl + (size_t)2 * CV * CV, WN4);
    conv_f16_2<<<WN4 / 256, 256>>>(Wo, woh, wol, WN4);

    // 1) QKV projections: 2-product fp16 emulation on tensor cores
    hgemm2<<<dim3(CV / 128, MV / 128, 3), 256, GEMM_SMEM>>>(xh, wh, wl, q, k, v);
    // 2) RoPE + bf16 hi/lo q,k
    rope_conv<<<(BV * TV * HV * 32) / 256, 256>>>();
    // 3) v transpose + hi/lo
    vtrans<<<dim3(TV / 64, BV * HV), 256>>>();
    // 4) Retention (bf16 3-term, unchanged) + GroupNorm -> fp16 g_xh
    retention_mma<<<dim3(TV / 64, BV * HV), 128, ATTN_SMEM>>>(gnw, gnb);
    // 5) Output projection: 2-product fp16 emulation
    hgemm2<<<dim3(CV / 128, MV / 128, 1), 256, GEMM_SMEM>>>(xh, woh, wol, out, out, out);
}

// round 16
// speedup vs baseline: 1.4004x; 1.1262x over previous
#include <cuda_runtime.h>
#include <cuda_bf16.h>
#include <cuda_fp16.h>
#include <math.h>
#include <stdint.h>

#define BV 2
#define TV 2048
#define CV 1024
#define HV 16
#define DHV 64
#define MV (BV * TV)   // 4096

// ---------------------------------------------------------------------------
// Scratch (__device__ globals; allocation-free rule)
// ---------------------------------------------------------------------------
__device__ float g_q[(size_t)MV * CV];
__device__ float g_k[(size_t)MV * CV];
__device__ float g_v[(size_t)MV * CV];

__device__ __half g_xh[(size_t)MV * CV];          // fp16 x (then normed y) single limb
__device__ __half g_wh[(size_t)3 * CV * CV];      // Wq,Wk,Wv hi limb (fp16)
__device__ __half g_wl[(size_t)3 * CV * CV];      // Wq,Wk,Wv lo limb (fp16)
__device__ __half g_woh[(size_t)CV * CV];         // Wo hi
__device__ __half g_wol[(size_t)CV * CV];         // Wo lo

__device__ __half g_qf[(size_t)MV * CV];          // roped q, fp16 single limb
__device__ __half g_kh[(size_t)MV * CV];          // roped k, fp16 hi/lo
__device__ __half g_kl[(size_t)MV * CV];
__device__ __half g_vth[(size_t)MV * CV];         // v^T fp16 hi/lo  [bh][d][t]
__device__ __half g_vtl[(size_t)MV * CV];

// ---------------------------------------------------------------------------
// helpers
// ---------------------------------------------------------------------------
__device__ __forceinline__ uint32_t smem_to_u32(const void* p) {
    uint32_t a;
    asm("{ .reg .u64 t; cvta.to.shared.u64 t, %1; cvt.u32.u64 %0, t; }"
        : "=r"(a) : "l"(p));
    return a;
}
__device__ __forceinline__ void cp16(uint32_t saddr, const void* g) {
    asm volatile("cp.async.cg.shared.global [%0], [%1], 16;"
                 :: "r"(saddr), "l"(g) : "memory");
}
__device__ __forceinline__ void cp_commit() {
    asm volatile("cp.async.commit_group;" ::: "memory");
}
__device__ __forceinline__ void cp_wait1() {
    asm volatile("cp.async.wait_group 1;" ::: "memory");
}
__device__ __forceinline__ void cp_wait0() {
    asm volatile("cp.async.wait_group 0;" ::: "memory");
}
__device__ __forceinline__ void ldsm4(uint32_t& r0, uint32_t& r1,
                                      uint32_t& r2, uint32_t& r3, uint32_t addr) {
    asm volatile("ldmatrix.sync.aligned.m8n8.x4.shared.b16 {%0,%1,%2,%3}, [%4];"
                 : "=r"(r0), "=r"(r1), "=r"(r2), "=r"(r3) : "r"(addr));
}
__device__ __forceinline__ void mma_f16(float* c, const uint32_t* a, const uint32_t* b) {
    asm volatile(
        "mma.sync.aligned.m16n8k16.row.col.f32.f16.f16.f32 "
        "{%0,%1,%2,%3}, {%4,%5,%6,%7}, {%8,%9}, {%0,%1,%2,%3};"
        : "+f"(c[0]), "+f"(c[1]), "+f"(c[2]), "+f"(c[3])
        : "r"(a[0]), "r"(a[1]), "r"(a[2]), "r"(a[3]), "r"(b[0]), "r"(b[1]));
}
__device__ __forceinline__ float fast_exp2(float x) {
    float r;
    asm("ex2.approx.f32 %0, %1;" : "=f"(r) : "f"(x));
    return r;
}
__device__ __forceinline__ uint32_t pack_f16(float lo, float hi) {
    __half2 p = __floats2half2_rn(lo, hi);
    return *(uint32_t*)&p;
}

// ---------------------------------------------------------------------------
// fp32 -> fp16 single limb (vec4)
// ---------------------------------------------------------------------------
__global__ void conv_f16(const float* __restrict__ src, __half* __restrict__ dst, int n4)
{
    int i = blockIdx.x * blockDim.x + threadIdx.x;
    if (i >= n4) return;
    float4 v = ((const float4*)src)[i];
    __half2 a = __floats2half2_rn(v.x, v.y);
    __half2 b = __floats2half2_rn(v.z, v.w);
    ((uint2*)dst)[i] = make_uint2(*(uint32_t*)&a, *(uint32_t*)&b);
}

// ---------------------------------------------------------------------------
// fp32 -> (fp16 hi, fp16 lo) two-limb split (vec4)
// ---------------------------------------------------------------------------
__global__ void conv_f16_2(const float* __restrict__ src,
                           __half* __restrict__ hi, __half* __restrict__ lo, int n4)
{
    int i = blockIdx.x * blockDim.x + threadIdx.x;
    if (i >= n4) return;
    float4 v = ((const float4*)src)[i];
    __half h0 = __float2half_rn(v.x);
    __half h1 = __float2half_rn(v.y);
    __half h2 = __float2half_rn(v.z);
    __half h3 = __float2half_rn(v.w);
    __half l0 = __float2half_rn(v.x - __half2float(h0));
    __half l1 = __float2half_rn(v.y - __half2float(h1));
    __half l2 = __float2half_rn(v.z - __half2float(h2));
    __half l3 = __float2half_rn(v.w - __half2float(h3));
    __half2 hA = __halves2half2(h0, h1), hB = __halves2half2(h2, h3);
    __half2 lA = __halves2half2(l0, l1), lB = __halves2half2(l2, l3);
    ((uint2*)hi)[i] = make_uint2(*(uint32_t*)&hA, *(uint32_t*)&hB);
    ((uint2*)lo)[i] = make_uint2(*(uint32_t*)&lA, *(uint32_t*)&lB);
}

// ---------------------------------------------------------------------------
// Warp-MMA fp16 GEMM, 2-product emulation (unchanged from R15 PASS).
// ---------------------------------------------------------------------------
#define STAGE_BYTES 49152
#define OFF_A  0
#define OFF_BH 16384
#define OFF_BL 32768
#define GEMM_SMEM (2 * STAGE_BYTES)

__global__ __launch_bounds__(256)
void hgemm2(const __half* __restrict__ Ah,
            const __half* __restrict__ Wh0,
            const __half* __restrict__ Wl0,
            float* __restrict__ C0, float* __restrict__ C1, float* __restrict__ C2)
{
    extern __shared__ char smem[];
    const uint32_t sb = smem_to_u32(smem);
    const int tid = threadIdx.x;
    const int wid = tid >> 5;
    const int lane = tid & 31;
    const int z = blockIdx.z;

    const __half* Wh = Wh0 + (size_t)z * CV * CV;
    const __half* Wl = Wl0 + (size_t)z * CV * CV;
    float* C = (z == 0) ? C0 : ((z == 1) ? C1 : C2);

    const int bm = blockIdx.y * 128;
    const int bn = blockIdx.x * 128;
    const int warp_m = wid >> 1;
    const int warp_n = wid & 1;

    float c[2][8][4];
#pragma unroll
    for (int mb = 0; mb < 2; ++mb)
#pragma unroll
        for (int nb = 0; nb < 8; ++nb)
#pragma unroll
            for (int e = 0; e < 4; ++e) c[mb][nb][e] = 0.f;

    auto issue = [&](int ch, int stage) {
        const int kc0 = ch * 64;
        const uint32_t base = sb + stage * STAGE_BYTES;
#pragma unroll
        for (int it = 0; it < 4; ++it) {
            const int idx = it * 256 + tid;
            const int row = idx >> 3;
            const int colb = (idx & 7) * 16;
            const uint32_t sw = (uint32_t)(row * 128 + (colb ^ ((row & 7) << 4)));
            const size_t gA = (size_t)(bm + row) * CV + kc0 + (colb >> 1);
            const size_t gB = (size_t)(bn + row) * CV + kc0 + (colb >> 1);
            cp16(base + OFF_A + sw, Ah + gA);
            cp16(base + OFF_BH + sw, Wh + gB);
            cp16(base + OFF_BL + sw, Wl + gB);
        }
        cp_commit();
    };

    issue(0, 0);

    const int a_row16 = lane & 15;
    const int a_koffb = ((lane >> 4) & 1) * 16;
    const int b_rowsel = (lane & 7) + ((lane >> 4) & 1) * 8;
    const int b_koffb = ((lane >> 3) & 1) * 16;

    const int NT = 16;
    for (int ch = 0; ch < NT; ++ch) {
        if (ch + 1 < NT) issue(ch + 1, (ch + 1) & 1);
        if (ch + 1 < NT) cp_wait1(); else cp_wait0();
        __syncthreads();

        const uint32_t base = sb + (ch & 1) * STAGE_BYTES;
#pragma unroll
        for (int ks = 0; ks < 4; ++ks) {
            const int kb = ks * 32;

            uint32_t ah[2][4];
#pragma unroll
            for (int mb = 0; mb < 2; ++mb) {
                const int r = warp_m * 32 + mb * 16 + a_row16;
                const uint32_t ad = base + (uint32_t)(r * 128 +
                                     ((kb + a_koffb) ^ ((r & 7) << 4)));
                ldsm4(ah[mb][0], ah[mb][1], ah[mb][2], ah[mb][3], ad + OFF_A);
            }

            uint32_t bh[8][2], bl[8][2];
#pragma unroll
            for (int nq = 0; nq < 4; ++nq) {
                const int r = warp_n * 64 + nq * 16 + b_rowsel;
                const uint32_t bd = base + (uint32_t)(r * 128 +
                                     ((kb + b_koffb) ^ ((r & 7) << 4)));
                uint32_t t0, t1, t2, t3;
                ldsm4(t0, t1, t2, t3, bd + OFF_BH);
                bh[nq * 2][0] = t0; bh[nq * 2][1] = t1;
                bh[nq * 2 + 1][0] = t2; bh[nq * 2 + 1][1] = t3;
                ldsm4(t0, t1, t2, t3, bd + OFF_BL);
                bl[nq * 2][0] = t0; bl[nq * 2][1] = t1;
                bl[nq * 2 + 1][0] = t2; bl[nq * 2 + 1][1] = t3;
            }

#pragma unroll
            for (int mb = 0; mb < 2; ++mb)
#pragma unroll
                for (int nb = 0; nb < 8; ++nb) {
                    mma_f16(c[mb][nb], ah[mb], bh[nb]);
                    mma_f16(c[mb][nb], ah[mb], bl[nb]);
                }
        }
        __syncthreads();
    }

    const int gr = lane >> 2;
    const int gc = (lane & 3) * 2;
#pragma unroll
    for (int mb = 0; mb < 2; ++mb) {
        const int row0 = bm + warp_m * 32 + mb * 16 + gr;
#pragma unroll
        for (int nb = 0; nb < 8; ++nb) {
            const int col = bn + warp_n * 64 + nb * 8 + gc;
            *(float2*)(C + (size_t)row0 * CV + col) =
                make_float2(c[mb][nb][0], c[mb][nb][1]);
            *(float2*)(C + (size_t)(row0 + 8) * CV + col) =
                make_float2(c[mb][nb][2], c[mb][nb][3]);
        }
    }
}

// ---------------------------------------------------------------------------
// RoPE on q and k. q -> fp16 single limb; k -> fp16 hi/lo two limbs.
// ---------------------------------------------------------------------------
__global__ void rope_conv()
{
    const int idx = blockIdx.x * blockDim.x + threadIdx.x;
    const int j = idx & 31;
    const int h = (idx >> 5) & (HV - 1);
    const int t = (idx >> 9) & (TV - 1);
    const int b = idx >> 20;

    const float L2_10000 = 13.287712379549449f;
    const float invf = exp2f(-(float)j * (L2_10000 / 32.0f));
    const float ang = (float)t * invf;
    float sn, cs;
    sincosf(ang, &sn, &cs);

    const size_t base = (size_t)(b * TV + t) * CV + h * DHV + j;

    float q1 = g_q[base], q2 = g_q[base + 32];
    float qa = q1 * cs - q2 * sn;
    float qb = q2 * cs + q1 * sn;
    float k1 = g_k[base], k2 = g_k[base + 32];
    float ka = k1 * cs - k2 * sn;
    float kb = k2 * cs + k1 * sn;

    g_qf[base]      = __float2half_rn(qa);
    g_qf[base + 32] = __float2half_rn(qb);

    __half kha = __float2half_rn(ka);
    __half khb = __float2half_rn(kb);
    g_kh[base]      = kha;
    g_kh[base + 32] = khb;
    g_kl[base]      = __float2half_rn(ka - __half2float(kha));
    g_kl[base + 32] = __float2half_rn(kb - __half2float(khb));
}

// ---------------------------------------------------------------------------
// v transpose + fp16 hi/lo: g_v [b*T+t][h*64+d] -> g_vth/g_vtl [bh][d][t].
// ---------------------------------------------------------------------------
__global__ __launch_bounds__(256)
void vtrans()
{
    __shared__ float vt[64][65];
    const int bh = blockIdx.y;
    const int b = bh >> 4, h = bh & 15;
    const int t0 = blockIdx.x * 64;
    const int tid = threadIdx.x;

#pragma unroll
    for (int it = 0; it < 4; ++it) {
        const int idx = it * 256 + tid;
        const int row = idx >> 4;
        const int c4 = (idx & 15) * 4;
        float4 v = *(const float4*)(g_v + (size_t)(b * TV + t0 + row) * CV + h * DHV + c4);
        vt[row][c4 + 0] = v.x; vt[row][c4 + 1] = v.y;
        vt[row][c4 + 2] = v.z; vt[row][c4 + 3] = v.w;
    }
    __syncthreads();

#pragma unroll
    for (int it = 0; it < 4; ++it) {
        const int idx = it * 256 + tid;
        const int d = idx >> 4;
        const int tc = (idx & 15) * 4;
        float x0 = vt[tc + 0][d], x1 = vt[tc + 1][d];
        float x2 = vt[tc + 2][d], x3 = vt[tc + 3][d];
        uint32_t h01 = pack_f16(x0, x1);
        uint32_t h23 = pack_f16(x2, x3);
        __half2 H01 = *(__half2*)&h01, H23 = *(__half2*)&h23;
        uint32_t l01 = pack_f16(x0 - __low2float(H01), x1 - __high2float(H01));
        uint32_t l23 = pack_f16(x2 - __low2float(H23), x3 - __high2float(H23));
        const size_t off = (size_t)(bh * DHV + d) * TV + t0 + tc;
        *(uint2*)(g_vth + off) = make_uint2(h01, h23);
        *(uint2*)(g_vtl + off) = make_uint2(l01, l23);
    }
}

// ---------------------------------------------------------------------------
// Retention attention, fp16 2-product emulation throughout:
//   S = f16(q) @ (kh + kl)^T ;  O = f16(S) @ (vh + vl)
// R12 pipeline (split commit groups, wait -> __syncthreads -> read) kept.
// SMEM: q 8KB + kh/kl 8KB + vh/vl 8KB = 40KB.
// Fused GroupNorm epilogue -> fp16 g_xh (out-proj A operand).
// ---------------------------------------------------------------------------
#define AQF 0
#define AKH 8192
#define AKL 16384
#define AVH 24576
#define AVL 32768
#define ATTN_SMEM 40960

__global__ __launch_bounds__(128)
void retention_mma(const float* __restrict__ gn_w, const float* __restrict__ gn_b)
{
    extern __shared__ char smem[];
    const uint32_t sb = smem_to_u32(smem);
    const int tid = threadIdx.x;
    const int w = tid >> 5;
    const int lane = tid & 31;

    const int qt = (int)(gridDim.x - 1 - blockIdx.x);   // big tiles first
    const int bh = blockIdx.y;
    const int b = bh >> 4, h = bh & 15;
    const int tq0 = qt * 64;

    const int g = lane >> 2;
    const int t4 = lane & 3;

    const float gamma = 1.0f - __int_as_float((127 - 5 - h) << 23);
    const float l2g = log2f(gamma);
    const float ginv1 = fast_exp2(-l2g);
    const float ginv8 = fast_exp2(-8.0f * l2g);
    const float gpow8 = fast_exp2(8.0f * l2g);
    const float ctf = fast_exp2(-2.0f * (float)t4 * l2g);

    auto issueK = [&](int kt) {
        const int tk0 = kt * 64;
#pragma unroll
        for (int it = 0; it < 4; ++it) {
            const int idx = it * 128 + tid;
            const int row = idx >> 3;
            const int colb = (idx & 7) * 16;
            const uint32_t sw = (uint32_t)(row * 128 + (colb ^ ((row & 7) << 4)));
            const size_t gk = (size_t)(b * TV + tk0 + row) * CV + h * DHV + (colb >> 1);
            cp16(sb + AKH + sw, g_kh + gk);
            cp16(sb + AKL + sw, g_kl + gk);
        }
        cp_commit();
    };
    auto issueV = [&](int kt) {
        const int tk0 = kt * 64;
#pragma unroll
        for (int it = 0; it < 4; ++it) {
            const int idx = it * 128 + tid;
            const int row = idx >> 3;
            const int colb = (idx & 7) * 16;
            const uint32_t sw = (uint32_t)(row * 128 + (colb ^ ((row & 7) << 4)));
            const size_t gv = (size_t)(bh * DHV + row) * TV + tk0 + (colb >> 1);
            cp16(sb + AVH + sw, g_vth + gv);
            cp16(sb + AVL + sw, g_vtl + gv);
        }
        cp_commit();
    };

    // preload: q (single limb, 512 slots), then k0, v0 as separate groups
#pragma unroll
    for (int it = 0; it < 4; ++it) {
        const int idx = it * 128 + tid;
        const int row = idx >> 3;
        const int colb = (idx & 7) * 16;
        const uint32_t sw = (uint32_t)(row * 128 + (colb ^ ((row & 7) << 4)));
        const size_t gq = (size_t)(b * TV + tq0 + row) * CV + h * DHV + (colb >> 1);
        cp16(sb + AQF + sw, g_qf + gq);
    }
    cp_commit();
    issueK(0);
    issueV(0);

    cp_wait1();          // q + k0 complete for self
    __syncthreads();     // visible to all

    // persistent q fragments (single limb)
    uint32_t qf[4][4];
    {
        const int ar = w * 16 + (lane & 15);
        const int ak = ((lane >> 4) & 1) * 16;
#pragma unroll
        for (int ks = 0; ks < 4; ++ks) {
            const uint32_t ad = sb + (uint32_t)(ar * 128 + ((ks * 32 + ak) ^ ((ar & 7) << 4)));
            ldsm4(qf[ks][0], qf[ks][1], qf[ks][2], qf[ks][3], ad + AQF);
        }
    }

    float o[8][4];
#pragma unroll
    for (int nb = 0; nb < 8; ++nb)
#pragma unroll
        for (int e = 0; e < 4; ++e) o[nb][e] = 0.f;

    const int b_row = (lane & 7) + ((lane >> 4) & 1) * 8;
    const int b_koffb = ((lane >> 3) & 1) * 16;

    for (int kt = 0; kt <= qt; ++kt) {
        const int tk0 = kt * 64;

        // ---- S = f16(q) (kh + kl)^T ----
        float s[8][4];
#pragma unroll
        for (int nb = 0; nb < 8; ++nb)
#pragma unroll
            for (int e = 0; e < 4; ++e) s[nb][e] = 0.f;

#pragma unroll
        for (int ks = 0; ks < 4; ++ks) {
#pragma unroll
            for (int nq = 0; nq < 4; ++nq) {
                const int r = nq * 16 + b_row;
                const uint32_t bd = sb + (uint32_t)(r * 128 +
                                     ((ks * 32 + b_koffb) ^ ((r & 7) << 4)));
                uint32_t h0, h1, h2, h3, l0, l1, l2, l3;
                ldsm4(h0, h1, h2, h3, bd + AKH);
                ldsm4(l0, l1, l2, l3, bd + AKL);
                uint32_t bh0[2] = {h0, h1}, bh1[2] = {h2, h3};
                uint32_t bl0[2] = {l0, l1}, bl1[2] = {l2, l3};
                mma_f16(s[nq * 2],     qf[ks], bh0);
                mma_f16(s[nq * 2],     qf[ks], bl0);
                mma_f16(s[nq * 2 + 1], qf[ks], bh1);
                mma_f16(s[nq * 2 + 1], qf[ks], bl1);
            }
        }

        __syncthreads();
        if (kt < qt) { issueK(kt + 1); cp_wait1(); }
        else         { cp_wait0(); }
        __syncthreads();   // v(kt) visible to ALL threads

        // ---- decay * scale ----
        const int dbase = tq0 - tk0;
        const float rf0 = 0.125f * fast_exp2((float)(dbase + w * 16 + g) * l2g);
        const float rf8 = rf0 * gpow8;
        float cf = ctf;
        if (kt < qt) {
#pragma unroll
            for (int nb = 0; nb < 8; ++nb) {
                const float c0f = cf, c1f = cf * ginv1;
                s[nb][0] *= rf0 * c0f;
                s[nb][1] *= rf0 * c1f;
                s[nb][2] *= rf8 * c0f;
                s[nb][3] *= rf8 * c1f;
                cf *= ginv8;
            }
        } else {
            const int r0 = w * 16 + g, r1 = r0 + 8;
#pragma unroll
            for (int nb = 0; nb < 8; ++nb) {
                const int j0 = 8 * nb + 2 * t4;
                const float c0f = cf, c1f = cf * ginv1;
                s[nb][0] = (r0 >= j0)     ? s[nb][0] * rf0 * c0f : 0.f;
                s[nb][1] = (r0 >= j0 + 1) ? s[nb][1] * rf0 * c1f : 0.f;
                s[nb][2] = (r1 >= j0)     ? s[nb][2] * rf8 * c0f : 0.f;
                s[nb][3] = (r1 >= j0 + 1) ? s[nb][3] * rf8 * c1f : 0.f;
                cf *= ginv8;
            }
        }

        // ---- S -> fp16 A-fragments (single limb) ----
        uint32_t sa[4][4];
#pragma unroll
        for (int kc = 0; kc < 4; ++kc) {
            const int n0 = 2 * kc, n1 = 2 * kc + 1;
            sa[kc][0] = pack_f16(s[n0][0], s[n0][1]);
            sa[kc][1] = pack_f16(s[n0][2], s[n0][3]);
            sa[kc][2] = pack_f16(s[n1][0], s[n1][1]);
            sa[kc][3] = pack_f16(s[n1][2], s[n1][3]);
        }

        // ---- O += f16(S) (vh + vl) ----
#pragma unroll
        for (int kc = 0; kc < 4; ++kc) {
#pragma unroll
            for (int nq = 0; nq < 4; ++nq) {
                const int r = nq * 16 + b_row;
                const uint32_t bd = sb + (uint32_t)(r * 128 +
                                     ((kc * 32 + b_koffb) ^ ((r & 7) << 4)));
                uint32_t h0, h1, h2, h3, l0, l1, l2, l3;
                ldsm4(h0, h1, h2, h3, bd + AVH);
                ldsm4(l0, l1, l2, l3, bd + AVL);
                uint32_t vh0[2] = {h0, h1}, vh1[2] = {h2, h3};
                uint32_t vl0[2] = {l0, l1}, vl1[2] = {l2, l3};
                mma_f16(o[nq * 2],     sa[kc], vh0);
                mma_f16(o[nq * 2],     sa[kc], vl0);
                mma_f16(o[nq * 2 + 1], sa[kc], vh1);
                mma_f16(o[nq * 2 + 1], sa[kc], vl1);
            }
        }

        __syncthreads();
        if (kt < qt) {
            issueV(kt + 1);
            cp_wait1();
            __syncthreads();   // k(kt+1) visible to ALL threads
        }
    }

    // ---- fused GroupNorm + fp16 store into out-proj input ----
    float sum0 = 0.f, sq0 = 0.f, sum1 = 0.f, sq1 = 0.f;
#pragma unroll
    for (int nb = 0; nb < 8; ++nb) {
        sum0 += o[nb][0] + o[nb][1];
        sq0  += o[nb][0] * o[nb][0] + o[nb][1] * o[nb][1];
        sum1 += o[nb][2] + o[nb][3];
        sq1  += o[nb][2] * o[nb][2] + o[nb][3] * o[nb][3];
    }
#pragma unroll
    for (int off = 1; off < 4; off <<= 1) {
        sum0 += __shfl_xor_sync(0xffffffffu, sum0, off);
        sq0  += __shfl_xor_sync(0xffffffffu, sq0,  off);
        sum1 += __shfl_xor_sync(0xffffffffu, sum1, off);
        sq1  += __shfl_xor_sync(0xffffffffu, sq1,  off);
    }
    const float invn = 1.0f / 64.0f;
    const float mean0 = sum0 * invn;
    const float mean1 = sum1 * invn;
    const float rs0 = rsqrtf(sq0 * invn - mean0 * mean0 + 1e-5f);
    const float rs1 = rsqrtf(sq1 * invn - mean1 * mean1 + 1e-5f);

    const int row0 = tq0 + w * 16 + g;
    const size_t base0 = (size_t)(b * TV + row0) * CV + h * DHV;
    const size_t base1 = base0 + (size_t)8 * CV;

#pragma unroll
    for (int nb = 0; nb < 8; ++nb) {
        const int d0 = 8 * nb + 2 * t4;
        const float2 wv = *(const float2*)(gn_w + h * DHV + d0);
        const float2 bv = *(const float2*)(gn_b + h * DHV + d0);
        float y00 = (o[nb][0] - mean0) * rs0 * wv.x + bv.x;
        float y01 = (o[nb][1] - mean0) * rs0 * wv.y + bv.y;
        float y10 = (o[nb][2] - mean1) * rs1 * wv.x + bv.x;
        float y11 = (o[nb][3] - mean1) * rs1 * wv.y + bv.y;

        __half2 p0 = __floats2half2_rn(y00, y01);
        __half2 p1 = __floats2half2_rn(y10, y11);
        *(__half2*)(g_xh + base0 + d0) = p0;
        *(__half2*)(g_xh + base1 + d0) = p1;
    }
}

// ---------------------------------------------------------------------------
extern "C" void kernel_launch(void* const* d_in, const int* in_sizes, int n_in,
                              void* d_out, int out_size)
{
    const float* x   = (const float*)d_in[0];
    const float* Wq  = (const float*)d_in[1];
    const float* Wk  = (const float*)d_in[2];
    const float* Wv  = (const float*)d_in[3];
    const float* Wo  = (const float*)d_in[4];
    const float* gnw = (const float*)d_in[5];
    const float* gnb = (const float*)d_in[6];
    float* out = (float*)d_out;

    float *q, *k, *v;
    __half *xh, *wh, *wl, *woh, *wol;
    cudaGetSymbolAddress((void**)&q, g_q);
    cudaGetSymbolAddress((void**)&k, g_k);
    cudaGetSymbolAddress((void**)&v, g_v);
    cudaGetSymbolAddress((void**)&xh, g_xh);
    cudaGetSymbolAddress((void**)&wh, g_wh);
    cudaGetSymbolAddress((void**)&wl, g_wl);
    cudaGetSymbolAddress((void**)&woh, g_woh);
    cudaGetSymbolAddress((void**)&wol, g_wol);

    cudaFuncSetAttribute(hgemm2,
                         cudaFuncAttributeMaxDynamicSharedMemorySize, GEMM_SMEM);
    cudaFuncSetAttribute(retention_mma,
                         cudaFuncAttributeMaxDynamicSharedMemorySize, ATTN_SMEM);

    const int WN4 = CV * CV / 4;
    const int XN4 = MV * CV / 4;

    // 0) fp16 conversions: x single limb; weights two limbs
    conv_f16<<<XN4 / 256, 256>>>(x, xh, XN4);
    conv_f16_2<<<WN4 / 256, 256>>>(Wq, wh,                       wl,                       WN4);
    conv_f16_2<<<WN4 / 256, 256>>>(Wk, wh + (size_t)CV * CV,     wl + (size_t)CV * CV,     WN4);
    conv_f16_2<<<WN4 / 256, 256>>>(Wv, wh + (size_t)2 * CV * CV, wl + (size_t)2 * CV * CV, WN4);
    conv_f16_2<<<WN4 / 256, 256>>>(Wo, woh, wol, WN4);

    // 1) QKV projections: 2-product fp16 emulation on tensor cores
    hgemm2<<<dim3(CV / 128, MV / 128, 3), 256, GEMM_SMEM>>>(xh, wh, wl, q, k, v);
    // 2) RoPE: q -> fp16 single limb, k -> fp16 two limbs
    rope_conv<<<(BV * TV * HV * 32) / 256, 256>>>();
    // 3) v transpose -> fp16 two limbs
    vtrans<<<dim3(TV / 64, BV * HV), 256>>>();
    // 4) Retention (fp16 2-product) + GroupNorm -> fp16 g_xh
    retention_mma<<<dim3(TV / 64, BV * HV), 128, ATTN_SMEM>>>(gnw, gnb);
    // 5) Output projection: 2-product fp16 emulation
    hgemm2<<<dim3(CV / 128, MV / 128, 1), 256, GEMM_SMEM>>>(xh, woh, wol, out, out, out);
}